// round 10
// baseline (speedup 1.0000x reference)
#include <cuda_runtime.h>
#include <cuda_bf16.h>
#include <cuda_fp16.h>
#include <cstdint>
#include <math.h>

#define L_   2048
#define E_   1024
#define H_   16
#define D_   64
#define MBL_ 2048

// ---------------- device scratch (static; allocation-free) -----------------
__device__ __half g_e[(size_t)H_ * L_ * L_];    // exp(s), unnormalized, fp16

// fp16 operands for the big GEMMs (A single, B hi/lo)
__device__ __half g_xh[L_ * E_];
__device__ __half g_wh[4 * E_ * E_], g_wl[4 * E_ * E_];   // q,k,v,o
__device__ __half g_aoh[L_ * E_];
// fp16 attention operands, [H][L][64]
__device__ __half g_qh[H_ * L_ * D_];
__device__ __half g_kh[H_ * L_ * D_], g_kl[H_ * L_ * D_];
__device__ __half g_vh[H_ * L_ * D_];

// ============================ PTX helpers (sm_80+) ==========================
__device__ __forceinline__ uint32_t smem_u32(const void* p) {
    uint32_t a;
    asm("{ .reg .u64 t; cvta.to.shared.u64 t, %1; cvt.u32.u64 %0, t; }"
        : "=r"(a) : "l"(p));
    return a;
}
__device__ __forceinline__ void cp16(uint32_t dst, const void* src) {
    asm volatile("cp.async.cg.shared.global [%0], [%1], 16;" :: "r"(dst), "l"(src));
}
#define CP_COMMIT()  asm volatile("cp.async.commit_group;" ::: "memory")
#define CP_WAIT(n)   asm volatile("cp.async.wait_group %0;" :: "n"(n) : "memory")

__device__ __forceinline__ void ldsm4(uint32_t a[4], uint32_t addr) {
    asm volatile("ldmatrix.sync.aligned.m8n8.x4.shared.b16 {%0,%1,%2,%3}, [%4];"
        : "=r"(a[0]), "=r"(a[1]), "=r"(a[2]), "=r"(a[3]) : "r"(addr));
}
__device__ __forceinline__ void ldsm2(uint32_t a[2], uint32_t addr) {
    asm volatile("ldmatrix.sync.aligned.m8n8.x2.shared.b16 {%0,%1}, [%2];"
        : "=r"(a[0]), "=r"(a[1]) : "r"(addr));
}
__device__ __forceinline__ void ldsm2t(uint32_t a[2], uint32_t addr) {
    asm volatile("ldmatrix.sync.aligned.m8n8.x2.trans.shared.b16 {%0,%1}, [%2];"
        : "=r"(a[0]), "=r"(a[1]) : "r"(addr));
}
__device__ __forceinline__ void mma_fp(float d[4], const uint32_t a[4], const uint32_t b[2]) {
    asm volatile("mma.sync.aligned.m16n8k16.row.col.f32.f16.f16.f32 "
        "{%0,%1,%2,%3}, {%4,%5,%6,%7}, {%8,%9}, {%0,%1,%2,%3};"
        : "+f"(d[0]), "+f"(d[1]), "+f"(d[2]), "+f"(d[3])
        : "r"(a[0]), "r"(a[1]), "r"(a[2]), "r"(a[3]), "r"(b[0]), "r"(b[1]));
}

// fast exp on FMA pipe (no MUFU)
__device__ __forceinline__ float fexp(float x) {
    float z  = fmaxf(x, -80.f) * 1.4426950408889634f;
    float fz = z + 12582912.f;
    int   n  = __float_as_int(fz) - 0x4B400000;
    float f  = z - (float)n;
    float p  = 1.3333558146428443e-3f;
    p = fmaf(p, f, 9.6181291076284772e-3f);
    p = fmaf(p, f, 5.5504108664821580e-2f);
    p = fmaf(p, f, 2.4022650695910071e-1f);
    p = fmaf(p, f, 6.9314718055994531e-1f);
    p = fmaf(p, f, 1.0f);
    return p * __int_as_float((n + 127) << 23);
}

// relu(e * iz + tt) on a half2, returned as packed fp16x2
__device__ __forceinline__ uint32_t trelu2(uint32_t e, float iz, float tt) {
    float2 f = __half22float2(*(__half2*)&e);
    float t0 = fmaxf(fmaf(f.x, iz, tt), 0.f);
    float t1 = fmaxf(fmaf(f.y, iz, tt), 0.f);
    __half2 r = __floats2half2_rn(t0, t1);
    return *(uint32_t*)&r;
}

// ============================================================================
// fp32 -> fp16 conversions, one launch.
// ============================================================================
__global__ __launch_bounds__(256) void conv_all(
    const float* __restrict__ x,  const float* __restrict__ Wq,
    const float* __restrict__ Wk, const float* __restrict__ Wv,
    const float* __restrict__ Wo)
{
    int b = blockIdx.x;
    if (b < 2048) {
        int i = b * 256 + threadIdx.x;
        float4 v = ((const float4*)x)[i];
        __half2* hp = (__half2*)(g_xh + i * 4);
        hp[0] = __floats2half2_rn(v.x, v.y);
        hp[1] = __floats2half2_rn(v.z, v.w);
        return;
    }
    int wsel = (b - 2048) >> 10;
    int off  = (b - 2048) & 1023;
    const float* s = (wsel == 0) ? Wq : (wsel == 1) ? Wk : (wsel == 2) ? Wv : Wo;
    __half* hi = g_wh + (size_t)wsel * (E_ * E_);
    __half* lo = g_wl + (size_t)wsel * (E_ * E_);
    int i = off * 256 + threadIdx.x;
    float4 v = ((const float4*)s)[i];
    __half h0 = __float2half_rn(v.x), h1 = __float2half_rn(v.y);
    __half h2 = __float2half_rn(v.z), h3 = __float2half_rn(v.w);
    __half l0 = __float2half_rn(v.x - __half2float(h0));
    __half l1 = __float2half_rn(v.y - __half2float(h1));
    __half l2 = __float2half_rn(v.z - __half2float(h2));
    __half l3 = __float2half_rn(v.w - __half2float(h3));
    __half2* hp = (__half2*)(hi + i * 4);
    __half2* lp = (__half2*)(lo + i * 4);
    hp[0] = __halves2half2(h0, h1); hp[1] = __halves2half2(h2, h3);
    lp[0] = __halves2half2(l0, l1); lp[1] = __halves2half2(l2, l3);
}

// ============================================================================
// fp16x2 GEMM on mma.sync: C[128,64] = A[M,K] * (Bh+Bl)[N,K]^T, 2 terms.
// 256 thr = 8 warps (4m x 2n), warp tile 32x32; 2 CTAs/SM.
// mode 0: x*W[z] -> q fp16 / k fp16 hi,lo / v fp16 in [H][L][64]
// mode 1: ao*Wo -> out fp32
// ============================================================================
#define BK     64
#define NCHK   (E_ / BK)
#define TILEA  (128 * 128)          // 16 KB: 128 rows x BK fp16
#define TILEBB (64 * 128)           // 8 KB: 64 rows x BK fp16
#define STAGEB (TILEA + 2 * TILEBB) // 32 KB
#define SMEM_MMA (2 * STAGEB)       // 64 KB

__device__ __forceinline__ void load_a_async(
    uint32_t dst, const __half* src, int row0, int kt, int tid)
{
#pragma unroll
    for (int it = 0; it < 4; it++) {
        int c = tid + it * 256;
        int row = c >> 3;
        int ch  = c & 7;
        uint32_t sw = row * 128 + ((ch ^ (row & 7)) << 4);
        cp16(dst + sw, src + (size_t)(row0 + row) * E_ + kt + ch * 8);
    }
}
__device__ __forceinline__ void load_b_async(
    uint32_t dst, const __half* src, int row0, int kt, int tid)
{
#pragma unroll
    for (int it = 0; it < 2; it++) {
        int c = tid + it * 256;
        int row = c >> 3;
        int ch  = c & 7;
        uint32_t sw = row * 128 + ((ch ^ (row & 7)) << 4);
        cp16(dst + sw, src + (size_t)(row0 + row) * E_ + kt + ch * 8);
    }
}

__global__ void __launch_bounds__(256, 2) mma_gemm(int mode, float* __restrict__ out)
{
    extern __shared__ char smem[];
    uint32_t sbase = smem_u32(smem);
    int tid  = threadIdx.x;
    int lane = tid & 31;
    int w    = tid >> 5;
    int wm   = w >> 1;               // 0..3
    int wn   = w & 1;                // 0..1
    int z    = blockIdx.z;
    int m0   = blockIdx.y * 128;
    int n0   = blockIdx.x * 64;

    const __half* A = (mode == 0) ? g_xh : g_aoh;
    int wsel = (mode == 0) ? z : 3;
    const __half* Bhi = g_wh + (size_t)wsel * (E_ * E_);
    const __half* Blo = g_wl + (size_t)wsel * (E_ * E_);

    float acc[2][4][4];
#pragma unroll
    for (int mi = 0; mi < 2; mi++)
#pragma unroll
        for (int ni = 0; ni < 4; ni++)
#pragma unroll
            for (int r = 0; r < 4; r++) acc[mi][ni][r] = 0.f;

    int rl = lane & 7;
    int ai = lane >> 3;
    int aci = ai >> 1;
    int arow[2];
#pragma unroll
    for (int mi = 0; mi < 2; mi++)
        arow[mi] = (wm * 32 + mi * 16 + (ai & 1) * 8 + rl) * 128;
    int bi = ai & 1;
    int brow[4];
#pragma unroll
    for (int ni = 0; ni < 4; ni++)
        brow[ni] = (wn * 32 + ni * 8 + rl) * 128;

    load_a_async(sbase + 0,                 A,   m0, 0, tid);
    load_b_async(sbase + TILEA,             Bhi, n0, 0, tid);
    load_b_async(sbase + TILEA + TILEBB,    Blo, n0, 0, tid);
    CP_COMMIT();

    for (int kt = 0; kt < NCHK; kt++) {
        bool more = (kt + 1) < NCHK;
        if (more) {
            uint32_t nb = sbase + ((kt + 1) & 1) * STAGEB;
            int kk = (kt + 1) * BK;
            load_a_async(nb + 0,              A,   m0, kk, tid);
            load_b_async(nb + TILEA,          Bhi, n0, kk, tid);
            load_b_async(nb + TILEA + TILEBB, Blo, n0, kk, tid);
            CP_COMMIT();
            CP_WAIT(1);
        } else {
            CP_WAIT(0);
        }
        __syncthreads();

        uint32_t st = sbase + (kt & 1) * STAGEB;
#pragma unroll
        for (int ks = 0; ks < 4; ks++) {
            uint32_t af[2][4];
            uint32_t choA = (((ks * 2 + aci) ^ rl) << 4);
            uint32_t choB = (((ks * 2 + bi) ^ rl) << 4);
#pragma unroll
            for (int mi = 0; mi < 2; mi++)
                ldsm4(af[mi], st + arow[mi] + choA);
#pragma unroll
            for (int t = 0; t < 2; t++) {
                uint32_t uB = st + TILEA + t * TILEBB;
                uint32_t bf[4][2];
#pragma unroll
                for (int ni = 0; ni < 4; ni++)
                    ldsm2(bf[ni], uB + brow[ni] + choB);
#pragma unroll
                for (int mi = 0; mi < 2; mi++)
#pragma unroll
                    for (int ni = 0; ni < 4; ni++)
                        mma_fp(acc[mi][ni], af[mi], bf[ni]);
            }
        }
        __syncthreads();
    }

    int mrow = m0 + wm * 32 + (lane >> 2);
    int ncol = n0 + wn * 32 + (lane & 3) * 2;
#pragma unroll
    for (int mi = 0; mi < 2; mi++) {
#pragma unroll
        for (int ni = 0; ni < 4; ni++) {
            int n = ncol + ni * 8;
#pragma unroll
            for (int half = 0; half < 2; half++) {
                int m = mrow + mi * 16 + half * 8;
                float v0 = acc[mi][ni][half * 2], v1 = acc[mi][ni][half * 2 + 1];
                if (mode == 0) {
                    size_t o = ((size_t)(n >> 6) * L_ + m) * 64 + (n & 63);
                    if (z == 0) {
                        *(__half2*)(g_qh + o) = __floats2half2_rn(v0, v1);
                    } else if (z == 1) {
                        __half h0 = __float2half_rn(v0), h1 = __float2half_rn(v1);
                        __half l0 = __float2half_rn(v0 - __half2float(h0));
                        __half l1 = __float2half_rn(v1 - __half2float(h1));
                        *(__half2*)(g_kh + o) = __halves2half2(h0, h1);
                        *(__half2*)(g_kl + o) = __halves2half2(l0, l1);
                    } else {
                        *(__half2*)(g_vh + o) = __floats2half2_rn(v0, v1);
                    }
                } else {
                    *(float2*)(out + (size_t)m * E_ + n) = make_float2(v0, v1);
                }
            }
        }
    }
}

// ============================================================================
// Attention. CTA (p, h) handles 64-row q-tiles {31-p, p}.
// 256 thr = 8 warps: 4 m-warps x 2 n-warps, warp tile 16x32.
// Pass 1: S = q*(kh+kl) fp16 mma, e = fexp(s*scale+bias) -> g_e fp16, Z sums.
// Pass 2: e reloaded per-thread in A-frag layout (no smem/ldsm for T),
//         t = relu(e*invZ + tau/idx) in regs; O += T*V; O -> g_aoh fp16.
// ============================================================================
#define AT_    0u          /* 8 KB: Q (pass1 only) */
#define AKV_   8192u       /* 2 bufs x 16 KB (K: hi 8K + lo 8K; V: hi only) */
#define ABIAS_ 40960u      /* 8 KB */
#define AZP_   49152u      /* 2 x 64 floats */
#define AINVZ_ 49664u
#define ATAUT_ 49920u
#define SMEM_ATT 50176

__global__ __launch_bounds__(256) void attn_kernel(
    const float* __restrict__ bias, const float* __restrict__ tau)
{
    extern __shared__ char smem[];
    uint32_t sb = smem_u32(smem);
    float* sbias = (float*)(smem + ABIAS_);
    float* szp   = (float*)(smem + AZP_);
    float* sinvz = (float*)(smem + AINVZ_);
    float* staut = (float*)(smem + ATAUT_);

    int h   = blockIdx.y;
    int p   = blockIdx.x;           // 0..15
    int tid = threadIdx.x;
    int lane = tid & 31, w = tid >> 5;
    int wm = w >> 1, wn = w & 1;    // 4 m-warps x 2 n-warps
    int rl = lane & 7;
    int ai = lane >> 3, aci = ai >> 1, bi = ai & 1;
    float tauh = tau[h];
    const float scale = 0.125f;

    for (int i = tid; i < MBL_ / 4; i += 256)
        *(float4*)&sbias[i * 4] = *(const float4*)&bias[h * MBL_ + i * 4];

    const __half* qh = g_qh + (size_t)h * (L_ * 64);
    const __half* kh = g_kh + (size_t)h * (L_ * 64);
    const __half* kl = g_kl + (size_t)h * (L_ * 64);
    const __half* vh = g_vh + (size_t)h * (L_ * 64);
    __half* eh = g_e + (size_t)h * L_ * L_;

    uint32_t arow = (uint32_t)((wm * 16 + (ai & 1) * 8 + rl) * 128);
    uint32_t brow[4];
#pragma unroll
    for (int ni = 0; ni < 4; ni++)
        brow[ni] = (uint32_t)((wn * 32 + ni * 8 + rl) * 128);

    for (int which = 0; which < 2; which++) {
        int iq = which ? p : (31 - p);
        int q0 = iq * 64;
        int nch = iq + 1;

        __syncthreads();            // previous tile fully done with smem

        // ---- load Q (fp16, 64 rows x 128B) + K chunk 0 hi/lo ----
#pragma unroll
        for (int it = 0; it < 2; it++) {
            int c = tid + it * 256;
            int row = c >> 3, ch = c & 7;
            uint32_t sw = row * 128 + ((ch ^ (row & 7)) << 4);
            cp16(sb + AT_ + sw, qh + (size_t)(q0 + row) * 64 + ch * 8);
            cp16(sb + AKV_ + sw,        kh + (size_t)row * 64 + ch * 8);
            cp16(sb + AKV_ + 8192 + sw, kl + (size_t)row * 64 + ch * 8);
        }
        CP_COMMIT();

        float rs[2] = {0.f, 0.f};

        // ==================== PASS 1 ====================
        for (int j = 0; j < nch; j++) {
            int b = j & 1;
            int k0 = j * 64;
            if (j + 1 < nch) {
                uint32_t nb = sb + AKV_ + (b ^ 1) * 16384;
                int k0n = (j + 1) * 64;
#pragma unroll
                for (int it = 0; it < 2; it++) {
                    int c = tid + it * 256;
                    int row = c >> 3, ch = c & 7;
                    uint32_t sw = row * 128 + ((ch ^ (row & 7)) << 4);
                    cp16(nb + sw,        kh + (size_t)(k0n + row) * 64 + ch * 8);
                    cp16(nb + 8192 + sw, kl + (size_t)(k0n + row) * 64 + ch * 8);
                }
                CP_COMMIT();
                CP_WAIT(1);
            } else {
                CP_WAIT(0);
            }
            __syncthreads();

            float sacc[4][4];
#pragma unroll
            for (int ni = 0; ni < 4; ni++)
#pragma unroll
                for (int r = 0; r < 4; r++) sacc[ni][r] = 0.f;

            uint32_t bkh = sb + AKV_ + b * 16384;
            uint32_t bkl = bkh + 8192;
#pragma unroll
            for (int ks = 0; ks < 4; ks++) {
                uint32_t qf[4], khf[4][2], klf[4][2];
                uint32_t choA = (((ks * 2 + aci) ^ rl) << 4);
                uint32_t choB = (((ks * 2 + bi) ^ rl) << 4);
                ldsm4(qf, sb + AT_ + arow + choA);
#pragma unroll
                for (int ni = 0; ni < 4; ni++) {
                    ldsm2(khf[ni], bkh + brow[ni] + choB);
                    ldsm2(klf[ni], bkl + brow[ni] + choB);
                }
#pragma unroll
                for (int ni = 0; ni < 4; ni++) {
                    mma_fp(sacc[ni], qf, khf[ni]);
                    mma_fp(sacc[ni], qf, klf[ni]);
                }
            }
            __syncthreads();    // K buf b reusable

            // epilogue: scale + bias + causal, exp, store e, Z partials
            int r = wm * 16 + (lane >> 2);
#pragma unroll
            for (int ni = 0; ni < 4; ni++) {
                int kk = k0 + wn * 32 + ni * 8 + (lane & 3) * 2;
#pragma unroll
                for (int hh = 0; hh < 2; hh++) {
                    int qq = q0 + r + hh * 8;
                    float s0 = sacc[ni][hh * 2]     * scale;
                    float s1 = sacc[ni][hh * 2 + 1] * scale;
                    int d0 = qq - kk, d1 = d0 - 1;
                    float e0 = (d0 >= 0) ? fexp(s0 + sbias[d0]) : 0.f;
                    float e1 = (d1 >= 0) ? fexp(s1 + sbias[d1]) : 0.f;
                    *(__half2*)(eh + (size_t)qq * L_ + kk) = __floats2half2_rn(e0, e1);
                    rs[hh] += e0 + e1;
                }
            }
        }

        // ---- finalize Z ----
#pragma unroll
        for (int hh = 0; hh < 2; hh++) {
            rs[hh] += __shfl_xor_sync(0xffffffffu, rs[hh], 1);
            rs[hh] += __shfl_xor_sync(0xffffffffu, rs[hh], 2);
        }
        if ((lane & 3) == 0) {
            int r0 = wm * 16 + (lane >> 2);
            szp[wn * 64 + r0]     = rs[0];
            szp[wn * 64 + r0 + 8] = rs[1];
        }
        __syncthreads();
        if (tid < 64) {
            float Zr = szp[tid] + szp[64 + tid];
            sinvz[tid] = 1.f / Zr;
            staut[tid] = tauh / (float)(q0 + tid + 1);
        }
        // prefetch V chunk 0 into buf 0
#pragma unroll
        for (int it = 0; it < 2; it++) {
            int c = tid + it * 256;
            int row = c >> 3, ch = c & 7;
            uint32_t sw = row * 128 + ((ch ^ (row & 7)) << 4);
            cp16(sb + AKV_ + sw, vh + (size_t)row * 64 + ch * 8);
        }
        CP_COMMIT();
        __syncthreads();

        // per-thread row constants for pass 2
        int rr = wm * 16 + (lane >> 2);
        float iz0 = sinvz[rr],     tt0 = staut[rr];
        float iz1 = sinvz[rr + 8], tt1 = staut[rr + 8];
        const __half* erow0 = eh + (size_t)(q0 + rr) * L_;
        const __half* erow1 = eh + (size_t)(q0 + rr + 8) * L_;

        // ==================== PASS 2 ====================
        float oacc[4][4];
#pragma unroll
        for (int ni = 0; ni < 4; ni++)
#pragma unroll
            for (int r = 0; r < 4; r++) oacc[ni][r] = 0.f;

        for (int j = 0; j < nch; j++) {
            int b = j & 1;
            int k0 = j * 64;
            if (j + 1 < nch) {
                uint32_t nb = sb + AKV_ + (b ^ 1) * 16384;
                int k0n = (j + 1) * 64;
#pragma unroll
                for (int it = 0; it < 2; it++) {
                    int c = tid + it * 256;
                    int row = c >> 3, ch = c & 7;
                    uint32_t sw = row * 128 + ((ch ^ (row & 7)) << 4);
                    cp16(nb + sw, vh + (size_t)(k0n + row) * 64 + ch * 8);
                }
                CP_COMMIT();
                CP_WAIT(1);
            } else {
                CP_WAIT(0);
            }
            __syncthreads();

            uint32_t bv = sb + AKV_ + b * 16384;
            int krl = lane & 15;
#pragma unroll
            for (int ks = 0; ks < 4; ks++) {
                // e reloaded directly in A-frag layout; relu+scale in regs
                int kb = k0 + ks * 16 + (lane & 3) * 2;
                uint32_t tf[4];
                tf[0] = trelu2(*(const uint32_t*)(erow0 + kb),     iz0, tt0);
                tf[1] = trelu2(*(const uint32_t*)(erow1 + kb),     iz1, tt1);
                tf[2] = trelu2(*(const uint32_t*)(erow0 + kb + 8), iz0, tt0);
                tf[3] = trelu2(*(const uint32_t*)(erow1 + kb + 8), iz1, tt1);

                int kr = ks * 16 + krl;
#pragma unroll
                for (int ni = 0; ni < 4; ni++) {
                    uint32_t vf[2];
                    uint32_t off = kr * 128 + (((wn * 4 + ni) ^ (kr & 7)) << 4);
                    ldsm2t(vf, bv + off);
                    mma_fp(oacc[ni], tf, vf);
                }
            }
            __syncthreads();    // V buf free for next chunk
        }

        // ---- O -> g_aoh fp16 ----
#pragma unroll
        for (int ni = 0; ni < 4; ni++) {
            int c = wn * 32 + ni * 8 + (lane & 3) * 2;
#pragma unroll
            for (int hh = 0; hh < 2; hh++) {
                int q = q0 + rr + hh * 8;
                float v0 = oacc[ni][hh * 2], v1 = oacc[ni][hh * 2 + 1];
                size_t o = (size_t)q * E_ + h * 64 + c;
                *(__half2*)(g_aoh + o) = __floats2half2_rn(v0, v1);
            }
        }
    }
}

// ============================================================================
extern "C" void kernel_launch(void* const* d_in, const int* in_sizes, int n_in,
                              void* d_out, int out_size)
{
    (void)in_sizes; (void)n_in; (void)out_size;
    const float* x    = (const float*)d_in[0];
    const float* Wq   = (const float*)d_in[1];
    const float* Wk   = (const float*)d_in[2];
    const float* Wv   = (const float*)d_in[3];
    const float* Wo   = (const float*)d_in[4];
    const float* bias = (const float*)d_in[5];
    const float* tau  = (const float*)d_in[6];
    float* out = (float*)d_out;

    cudaFuncSetAttribute(mma_gemm, cudaFuncAttributeMaxDynamicSharedMemorySize, SMEM_MMA);
    cudaFuncSetAttribute(attn_kernel, cudaFuncAttributeMaxDynamicSharedMemorySize, SMEM_ATT);

    conv_all<<<2048 + 4 * 1024, 256>>>(x, Wq, Wk, Wv, Wo);
    mma_gemm<<<dim3(E_ / 64, L_ / 128, 3), 256, SMEM_MMA>>>(0, nullptr);
    attn_kernel<<<dim3(16, H_), 256, SMEM_ATT>>>(bias, tau);
    mma_gemm<<<dim3(E_ / 64, L_ / 128, 1), 256, SMEM_MMA>>>(1, out);
}

// round 11
// speedup vs baseline: 1.1996x; 1.1996x over previous
#include <cuda_runtime.h>
#include <cuda_bf16.h>
#include <cuda_fp16.h>
#include <cstdint>
#include <math.h>

#define L_   2048
#define E_   1024
#define H_   16
#define D_   64
#define MBL_ 2048

// ---------------- device scratch (static; allocation-free) -----------------
__device__ __half g_e[(size_t)H_ * L_ * L_];    // exp(s), unnormalized, fp16

// fp16 operands for the big GEMMs
__device__ __half g_xh[L_ * E_];
__device__ __half g_wh[4 * E_ * E_], g_wl[4 * E_ * E_];   // lo used for Wo only
__device__ __half g_aoh[L_ * E_];
// fp16 attention operands, [H][L][64]
__device__ __half g_qh[H_ * L_ * D_];
__device__ __half g_kh[H_ * L_ * D_], g_kl[H_ * L_ * D_];
__device__ __half g_vh[H_ * L_ * D_];

// ============================ PTX helpers (sm_80+) ==========================
__device__ __forceinline__ uint32_t smem_u32(const void* p) {
    uint32_t a;
    asm("{ .reg .u64 t; cvta.to.shared.u64 t, %1; cvt.u32.u64 %0, t; }"
        : "=r"(a) : "l"(p));
    return a;
}
__device__ __forceinline__ void cp16(uint32_t dst, const void* src) {
    asm volatile("cp.async.cg.shared.global [%0], [%1], 16;" :: "r"(dst), "l"(src));
}
#define CP_COMMIT()  asm volatile("cp.async.commit_group;" ::: "memory")
#define CP_WAIT(n)   asm volatile("cp.async.wait_group %0;" :: "n"(n) : "memory")

__device__ __forceinline__ void ldsm4(uint32_t a[4], uint32_t addr) {
    asm volatile("ldmatrix.sync.aligned.m8n8.x4.shared.b16 {%0,%1,%2,%3}, [%4];"
        : "=r"(a[0]), "=r"(a[1]), "=r"(a[2]), "=r"(a[3]) : "r"(addr));
}
__device__ __forceinline__ void ldsm2(uint32_t a[2], uint32_t addr) {
    asm volatile("ldmatrix.sync.aligned.m8n8.x2.shared.b16 {%0,%1}, [%2];"
        : "=r"(a[0]), "=r"(a[1]) : "r"(addr));
}
__device__ __forceinline__ void ldsm2t(uint32_t a[2], uint32_t addr) {
    asm volatile("ldmatrix.sync.aligned.m8n8.x2.trans.shared.b16 {%0,%1}, [%2];"
        : "=r"(a[0]), "=r"(a[1]) : "r"(addr));
}
__device__ __forceinline__ void mma_fp(float d[4], const uint32_t a[4], const uint32_t b[2]) {
    asm volatile("mma.sync.aligned.m16n8k16.row.col.f32.f16.f16.f32 "
        "{%0,%1,%2,%3}, {%4,%5,%6,%7}, {%8,%9}, {%0,%1,%2,%3};"
        : "+f"(d[0]), "+f"(d[1]), "+f"(d[2]), "+f"(d[3])
        : "r"(a[0]), "r"(a[1]), "r"(a[2]), "r"(a[3]), "r"(b[0]), "r"(b[1]));
}

// fast exp on FMA pipe (no MUFU)
__device__ __forceinline__ float fexp(float x) {
    float z  = fmaxf(x, -80.f) * 1.4426950408889634f;
    float fz = z + 12582912.f;
    int   n  = __float_as_int(fz) - 0x4B400000;
    float f  = z - (float)n;
    float p  = 1.3333558146428443e-3f;
    p = fmaf(p, f, 9.6181291076284772e-3f);
    p = fmaf(p, f, 5.5504108664821580e-2f);
    p = fmaf(p, f, 2.4022650695910071e-1f);
    p = fmaf(p, f, 6.9314718055994531e-1f);
    p = fmaf(p, f, 1.0f);
    return p * __int_as_float((n + 127) << 23);
}

// ============================================================================
// fp32 -> fp16 conversions, one launch.
// blocks [0,2048): x -> g_xh single; [2048,6144): W (q,k,v single hi; o hi/lo)
// ============================================================================
__global__ __launch_bounds__(256) void conv_all(
    const float* __restrict__ x,  const float* __restrict__ Wq,
    const float* __restrict__ Wk, const float* __restrict__ Wv,
    const float* __restrict__ Wo)
{
    int b = blockIdx.x;
    if (b < 2048) {
        int i = b * 256 + threadIdx.x;
        float4 v = ((const float4*)x)[i];
        __half2* hp = (__half2*)(g_xh + i * 4);
        hp[0] = __floats2half2_rn(v.x, v.y);
        hp[1] = __floats2half2_rn(v.z, v.w);
        return;
    }
    int wsel = (b - 2048) >> 10;
    int off  = (b - 2048) & 1023;
    const float* s = (wsel == 0) ? Wq : (wsel == 1) ? Wk : (wsel == 2) ? Wv : Wo;
    __half* hi = g_wh + (size_t)wsel * (E_ * E_);
    int i = off * 256 + threadIdx.x;
    float4 v = ((const float4*)s)[i];
    __half h0 = __float2half_rn(v.x), h1 = __float2half_rn(v.y);
    __half h2 = __float2half_rn(v.z), h3 = __float2half_rn(v.w);
    __half2* hp = (__half2*)(hi + i * 4);
    hp[0] = __halves2half2(h0, h1); hp[1] = __halves2half2(h2, h3);
    if (wsel == 3) {                  // only Wo keeps a lo correction
        __half l0 = __float2half_rn(v.x - __half2float(h0));
        __half l1 = __float2half_rn(v.y - __half2float(h1));
        __half l2 = __float2half_rn(v.z - __half2float(h2));
        __half l3 = __float2half_rn(v.w - __half2float(h3));
        __half2* lp = (__half2*)(g_wl + (size_t)wsel * (E_ * E_) + i * 4);
        lp[0] = __halves2half2(l0, l1); lp[1] = __halves2half2(l2, l3);
    }
}

// ============================================================================
// fp16 GEMM on mma.sync: C[128,128] = A[M,K] * B[N,K]^T
// mode 0: 1 term (Wh only), x*W[z] -> q fp16 / k fp16 hi,lo / v fp16
// mode 1: 2 terms (Wh+Wl), ao*Wo -> out fp32
// ============================================================================
#define BK    64
#define NCHK  (E_ / BK)
#define TILEB (128 * BK * 2)        // 16 KB per 128xBK fp16 tile
#define STAGEB (3 * TILEB)          // A, Bh, Bl = 48 KB
#define SMEM_MMA (2 * STAGEB)       // 96 KB

__device__ __forceinline__ void load_tile_async(
    uint32_t dst, const __half* src, int row0, int kt, int tid)
{
#pragma unroll
    for (int it = 0; it < 4; it++) {
        int c = tid + it * 256;
        int row = c >> 3;
        int ch  = c & 7;
        const __half* sp = src + (size_t)(row0 + row) * E_ + kt + ch * 8;
        uint32_t sw = row * 128 + ((ch ^ (row & 7)) << 4);
        cp16(dst + sw, sp);
    }
}

__global__ __launch_bounds__(256) void mma_gemm(int mode, float* __restrict__ out)
{
    extern __shared__ char smem[];
    uint32_t sbase = smem_u32(smem);
    int tid  = threadIdx.x;
    int lane = tid & 31;
    int w    = tid >> 5;
    int wm   = w >> 2;
    int wn   = w & 3;
    int z    = blockIdx.z;
    int m0   = blockIdx.y * 128;
    int n0   = blockIdx.x * 128;

    const __half* A = (mode == 0) ? g_xh : g_aoh;
    int wsel = (mode == 0) ? z : 3;
    const __half* Bhi = g_wh + (size_t)wsel * (E_ * E_);
    const __half* Blo = g_wl + (size_t)wsel * (E_ * E_);
    int nt = (mode == 0) ? 1 : 2;

    float acc[4][4][4];
#pragma unroll
    for (int mi = 0; mi < 4; mi++)
#pragma unroll
        for (int ni = 0; ni < 4; ni++)
#pragma unroll
            for (int r = 0; r < 4; r++) acc[mi][ni][r] = 0.f;

    int rl = lane & 7;
    int ai = lane >> 3;
    int aci = ai >> 1;
    int arow[4];
#pragma unroll
    for (int mi = 0; mi < 4; mi++)
        arow[mi] = (wm * 64 + mi * 16 + (ai & 1) * 8 + rl) * 128;
    int bi = (lane >> 3) & 1;
    int brow[4];
#pragma unroll
    for (int ni = 0; ni < 4; ni++)
        brow[ni] = (wn * 32 + ni * 8 + rl) * 128;

    load_tile_async(sbase + 0 * TILEB, A,   m0, 0, tid);
    load_tile_async(sbase + 1 * TILEB, Bhi, n0, 0, tid);
    if (nt == 2) load_tile_async(sbase + 2 * TILEB, Blo, n0, 0, tid);
    CP_COMMIT();

    for (int kt = 0; kt < NCHK; kt++) {
        bool more = (kt + 1) < NCHK;
        if (more) {
            uint32_t nb = sbase + ((kt + 1) & 1) * STAGEB;
            int kk = (kt + 1) * BK;
            load_tile_async(nb + 0 * TILEB, A,   m0, kk, tid);
            load_tile_async(nb + 1 * TILEB, Bhi, n0, kk, tid);
            if (nt == 2) load_tile_async(nb + 2 * TILEB, Blo, n0, kk, tid);
            CP_COMMIT();
            CP_WAIT(1);
        } else {
            CP_WAIT(0);
        }
        __syncthreads();

        uint32_t st = sbase + (kt & 1) * STAGEB;
#pragma unroll
        for (int ks = 0; ks < 4; ks++) {
            uint32_t af[4][4];
            uint32_t choA = (((ks * 2 + aci) ^ rl) << 4);
            uint32_t choB = (((ks * 2 + bi) ^ rl) << 4);
#pragma unroll
            for (int mi = 0; mi < 4; mi++)
                ldsm4(af[mi], st + arow[mi] + choA);
            for (int t = 0; t < nt; t++) {
                uint32_t uB = st + TILEB + t * TILEB;
                uint32_t bf[4][2];
#pragma unroll
                for (int ni = 0; ni < 4; ni++)
                    ldsm2(bf[ni], uB + brow[ni] + choB);
#pragma unroll
                for (int mi = 0; mi < 4; mi++)
#pragma unroll
                    for (int ni = 0; ni < 4; ni++)
                        mma_fp(acc[mi][ni], af[mi], bf[ni]);
            }
        }
        __syncthreads();
    }

    int mrow = m0 + wm * 64 + (lane >> 2);
    int ncol = n0 + wn * 32 + (lane & 3) * 2;
#pragma unroll
    for (int mi = 0; mi < 4; mi++) {
#pragma unroll
        for (int ni = 0; ni < 4; ni++) {
            int n = ncol + ni * 8;
#pragma unroll
            for (int half = 0; half < 2; half++) {
                int m = mrow + mi * 16 + half * 8;
                float v0 = acc[mi][ni][half * 2], v1 = acc[mi][ni][half * 2 + 1];
                if (mode == 0) {
                    size_t o = ((size_t)(n >> 6) * L_ + m) * 64 + (n & 63);
                    if (z == 0) {
                        *(__half2*)(g_qh + o) = __floats2half2_rn(v0, v1);
                    } else if (z == 1) {
                        __half h0 = __float2half_rn(v0), h1 = __float2half_rn(v1);
                        __half l0 = __float2half_rn(v0 - __half2float(h0));
                        __half l1 = __float2half_rn(v1 - __half2float(h1));
                        *(__half2*)(g_kh + o) = __halves2half2(h0, h1);
                        *(__half2*)(g_kl + o) = __halves2half2(l0, l1);
                    } else {
                        *(__half2*)(g_vh + o) = __floats2half2_rn(v0, v1);
                    }
                } else {
                    *(float2*)(out + (size_t)m * E_ + n) = make_float2(v0, v1);
                }
            }
        }
    }
}

// ============================================================================
// Attention (round-9 / 227.4µs version). CTA (p, h): 64-row q-tiles {31-p, p}.
// Pass 1: S = q*(kh+kl) fp16 mma, e = fexp(s*scale+bias) -> g_e fp16, Z sums.
// Pass 2: t = relu(e*invZ + tau/idx) fp16 -> smem; O += T*V; O -> g_aoh fp16.
// ============================================================================
#define AT_    0u          /* 8 KB: Q (pass1) / T (pass2) */
#define AKV_   8192u       /* 2 bufs x 16 KB (K: hi 8K + lo 8K; V: hi only) */
#define ABIAS_ 40960u      /* 8 KB */
#define AZP_   49152u      /* 2 x 64 floats */
#define AINVZ_ 49664u
#define ATAUT_ 49920u
#define SMEM_ATT 50176

__global__ __launch_bounds__(256) void attn_kernel(
    const float* __restrict__ bias, const float* __restrict__ tau)
{
    extern __shared__ char smem[];
    uint32_t sb = smem_u32(smem);
    float* sbias = (float*)(smem + ABIAS_);
    float* szp   = (float*)(smem + AZP_);
    float* sinvz = (float*)(smem + AINVZ_);
    float* staut = (float*)(smem + ATAUT_);

    int h   = blockIdx.y;
    int p   = blockIdx.x;           // 0..15
    int tid = threadIdx.x;
    int lane = tid & 31, w = tid >> 5;
    int wm = w >> 1, wn = w & 1;    // 4 m-warps x 2 n-warps
    int rl = lane & 7;
    int ai = lane >> 3, aci = ai >> 1, bi = ai & 1;
    float tauh = tau[h];
    const float scale = 0.125f;

    for (int i = tid; i < MBL_ / 4; i += 256)
        *(float4*)&sbias[i * 4] = *(const float4*)&bias[h * MBL_ + i * 4];

    const __half* qh = g_qh + (size_t)h * (L_ * 64);
    const __half* kh = g_kh + (size_t)h * (L_ * 64);
    const __half* kl = g_kl + (size_t)h * (L_ * 64);
    const __half* vh = g_vh + (size_t)h * (L_ * 64);
    __half* eh = g_e + (size_t)h * L_ * L_;

    uint32_t arow = (uint32_t)((wm * 16 + (ai & 1) * 8 + rl) * 128);
    uint32_t brow[4];
#pragma unroll
    for (int ni = 0; ni < 4; ni++)
        brow[ni] = (uint32_t)((wn * 32 + ni * 8 + rl) * 128);

    for (int which = 0; which < 2; which++) {
        int iq = which ? p : (31 - p);
        int q0 = iq * 64;
        int nch = iq + 1;

        __syncthreads();            // previous tile fully done with smem

        // ---- load Q (fp16, 64 rows x 128B) + K chunk 0 hi/lo ----
#pragma unroll
        for (int it = 0; it < 2; it++) {
            int c = tid + it * 256;
            int row = c >> 3, ch = c & 7;
            uint32_t sw = row * 128 + ((ch ^ (row & 7)) << 4);
            cp16(sb + AT_ + sw, qh + (size_t)(q0 + row) * 64 + ch * 8);
            cp16(sb + AKV_ + sw,        kh + (size_t)row * 64 + ch * 8);
            cp16(sb + AKV_ + 8192 + sw, kl + (size_t)row * 64 + ch * 8);
        }
        CP_COMMIT();

        float rs[2] = {0.f, 0.f};

        // ==================== PASS 1 ====================
        for (int j = 0; j < nch; j++) {
            int b = j & 1;
            int k0 = j * 64;
            if (j + 1 < nch) {
                uint32_t nb = sb + AKV_ + (b ^ 1) * 16384;
                int k0n = (j + 1) * 64;
#pragma unroll
                for (int it = 0; it < 2; it++) {
                    int c = tid + it * 256;
                    int row = c >> 3, ch = c & 7;
                    uint32_t sw = row * 128 + ((ch ^ (row & 7)) << 4);
                    cp16(nb + sw,        kh + (size_t)(k0n + row) * 64 + ch * 8);
                    cp16(nb + 8192 + sw, kl + (size_t)(k0n + row) * 64 + ch * 8);
                }
                CP_COMMIT();
                CP_WAIT(1);
            } else {
                CP_WAIT(0);
            }
            __syncthreads();

            float sacc[4][4];
#pragma unroll
            for (int ni = 0; ni < 4; ni++)
#pragma unroll
                for (int r = 0; r < 4; r++) sacc[ni][r] = 0.f;

            uint32_t bkh = sb + AKV_ + b * 16384;
            uint32_t bkl = bkh + 8192;
#pragma unroll
            for (int ks = 0; ks < 4; ks++) {
                uint32_t qf[4], khf[4][2], klf[4][2];
                uint32_t choA = (((ks * 2 + aci) ^ rl) << 4);
                uint32_t choB = (((ks * 2 + bi) ^ rl) << 4);
                ldsm4(qf, sb + AT_ + arow + choA);
#pragma unroll
                for (int ni = 0; ni < 4; ni++) {
                    ldsm2(khf[ni], bkh + brow[ni] + choB);
                    ldsm2(klf[ni], bkl + brow[ni] + choB);
                }
#pragma unroll
                for (int ni = 0; ni < 4; ni++) {
                    mma_fp(sacc[ni], qf, khf[ni]);
                    mma_fp(sacc[ni], qf, klf[ni]);
                }
            }
            __syncthreads();    // K buf b reusable

            // epilogue: scale + bias + causal, exp, store e, Z partials
            int r = wm * 16 + (lane >> 2);
#pragma unroll
            for (int ni = 0; ni < 4; ni++) {
                int kk = k0 + wn * 32 + ni * 8 + (lane & 3) * 2;
#pragma unroll
                for (int hh = 0; hh < 2; hh++) {
                    int qq = q0 + r + hh * 8;
                    float s0 = sacc[ni][hh * 2]     * scale;
                    float s1 = sacc[ni][hh * 2 + 1] * scale;
                    int d0 = qq - kk, d1 = d0 - 1;
                    float e0 = (d0 >= 0) ? fexp(s0 + sbias[d0]) : 0.f;
                    float e1 = (d1 >= 0) ? fexp(s1 + sbias[d1]) : 0.f;
                    *(__half2*)(eh + (size_t)qq * L_ + kk) = __floats2half2_rn(e0, e1);
                    rs[hh] += e0 + e1;
                }
            }
        }

        // ---- finalize Z ----
#pragma unroll
        for (int hh = 0; hh < 2; hh++) {
            rs[hh] += __shfl_xor_sync(0xffffffffu, rs[hh], 1);
            rs[hh] += __shfl_xor_sync(0xffffffffu, rs[hh], 2);
        }
        if ((lane & 3) == 0) {
            int r0 = wm * 16 + (lane >> 2);
            szp[wn * 64 + r0]     = rs[0];
            szp[wn * 64 + r0 + 8] = rs[1];
        }
        __syncthreads();
        if (tid < 64) {
            float Zr = szp[tid] + szp[64 + tid];
            sinvz[tid] = 1.f / Zr;
            staut[tid] = tauh / (float)(q0 + tid + 1);
        }
        // prefetch V chunk 0 into buf 0
#pragma unroll
        for (int it = 0; it < 2; it++) {
            int c = tid + it * 256;
            int row = c >> 3, ch = c & 7;
            uint32_t sw = row * 128 + ((ch ^ (row & 7)) << 4);
            cp16(sb + AKV_ + sw, vh + (size_t)row * 64 + ch * 8);
        }
        CP_COMMIT();
        __syncthreads();

        // ==================== PASS 2 ====================
        float oacc[4][4];
#pragma unroll
        for (int ni = 0; ni < 4; ni++)
#pragma unroll
            for (int r = 0; r < 4; r++) oacc[ni][r] = 0.f;

        for (int j = 0; j < nch; j++) {
            int b = j & 1;
            int k0 = j * 64;
            // build T tile (fp16) in AT_ (prev chunk's MMA done: trailing sync)
#pragma unroll
            for (int it = 0; it < 2; it++) {
                int c = tid + it * 256;
                int row = c >> 3, ch = c & 7;
                uint4 ev = *(const uint4*)(eh + (size_t)(q0 + row) * L_ + k0 + ch * 8);
                float iz = sinvz[row], tt = staut[row];
                const __half2* ep = (const __half2*)&ev;
                uint32_t tw[4];
#pragma unroll
                for (int u = 0; u < 4; u++) {
                    float2 e2 = __half22float2(ep[u]);
                    float t0 = fmaxf(fmaf(e2.x, iz, tt), 0.f);
                    float t1 = fmaxf(fmaf(e2.y, iz, tt), 0.f);
                    __half2 tp = __floats2half2_rn(t0, t1);
                    tw[u] = *(uint32_t*)&tp;
                }
                uint32_t sw = row * 128 + ((ch ^ (row & 7)) << 4);
                *(uint4*)(smem + AT_ + sw) = make_uint4(tw[0], tw[1], tw[2], tw[3]);
            }
            if (j + 1 < nch) {
                uint32_t nb = sb + AKV_ + (b ^ 1) * 16384;
                int k0n = (j + 1) * 64;
#pragma unroll
                for (int it = 0; it < 2; it++) {
                    int c = tid + it * 256;
                    int row = c >> 3, ch = c & 7;
                    uint32_t sw = row * 128 + ((ch ^ (row & 7)) << 4);
                    cp16(nb + sw, vh + (size_t)(k0n + row) * 64 + ch * 8);
                }
                CP_COMMIT();
                CP_WAIT(1);
            } else {
                CP_WAIT(0);
            }
            __syncthreads();

            uint32_t bv = sb + AKV_ + b * 16384;
            int krl = lane & 15;
#pragma unroll
            for (int ks = 0; ks < 4; ks++) {
                uint32_t tf[4], vf[4][2];
                uint32_t choA = (((ks * 2 + aci) ^ rl) << 4);
                ldsm4(tf, sb + AT_ + arow + choA);
                int kr = ks * 16 + krl;
#pragma unroll
                for (int ni = 0; ni < 4; ni++) {
                    uint32_t off = kr * 128 + (((wn * 4 + ni) ^ (kr & 7)) << 4);
                    ldsm2t(vf[ni], bv + off);
                }
#pragma unroll
                for (int ni = 0; ni < 4; ni++)
                    mma_fp(oacc[ni], tf, vf[ni]);
            }
            __syncthreads();    // T + V buf free for next chunk
        }

        // ---- O -> g_aoh fp16 ----
#pragma unroll
        for (int ni = 0; ni < 4; ni++) {
            int c = wn * 32 + ni * 8 + (lane & 3) * 2;
#pragma unroll
            for (int hh = 0; hh < 2; hh++) {
                int q = q0 + wm * 16 + (lane >> 2) + hh * 8;
                float v0 = oacc[ni][hh * 2], v1 = oacc[ni][hh * 2 + 1];
                size_t o = (size_t)q * E_ + h * 64 + c;
                *(__half2*)(g_aoh + o) = __floats2half2_rn(v0, v1);
            }
        }
    }
}

// ============================================================================
extern "C" void kernel_launch(void* const* d_in, const int* in_sizes, int n_in,
                              void* d_out, int out_size)
{
    (void)in_sizes; (void)n_in; (void)out_size;
    const float* x    = (const float*)d_in[0];
    const float* Wq   = (const float*)d_in[1];
    const float* Wk   = (const float*)d_in[2];
    const float* Wv   = (const float*)d_in[3];
    const float* Wo   = (const float*)d_in[4];
    const float* bias = (const float*)d_in[5];
    const float* tau  = (const float*)d_in[6];
    float* out = (float*)d_out;

    cudaFuncSetAttribute(mma_gemm, cudaFuncAttributeMaxDynamicSharedMemorySize, SMEM_MMA);
    cudaFuncSetAttribute(attn_kernel, cudaFuncAttributeMaxDynamicSharedMemorySize, SMEM_ATT);

    conv_all<<<2048 + 4 * 1024, 256>>>(x, Wq, Wk, Wv, Wo);
    mma_gemm<<<dim3(E_ / 128, L_ / 128, 3), 256, SMEM_MMA>>>(0, nullptr);
    attn_kernel<<<dim3(16, H_), 256, SMEM_ATT>>>(bias, tau);
    mma_gemm<<<dim3(E_ / 128, L_ / 128, 1), 256, SMEM_MMA>>>(1, out);
}

// round 12
// speedup vs baseline: 1.2664x; 1.0557x over previous
#include <cuda_runtime.h>
#include <cuda_bf16.h>
#include <cuda_fp16.h>
#include <cstdint>
#include <math.h>

#define L_   2048
#define E_   1024
#define H_   16
#define D_   64
#define MBL_ 2048

// ---------------- device scratch (static; allocation-free) -----------------
__device__ __half g_e[(size_t)H_ * L_ * L_];    // exp(s), unnormalized, fp16

// fp16 operands for the big GEMMs
__device__ __half g_xh[L_ * E_];
__device__ __half g_wh[4 * E_ * E_], g_wl[4 * E_ * E_];   // lo used for Wo only
__device__ __half g_aoh[L_ * E_];
// fp16 attention operands, [H][L][64] (all single-rounded)
__device__ __half g_qh[H_ * L_ * D_];
__device__ __half g_kh[H_ * L_ * D_];
__device__ __half g_vh[H_ * L_ * D_];

// ============================ PTX helpers (sm_80+) ==========================
__device__ __forceinline__ uint32_t smem_u32(const void* p) {
    uint32_t a;
    asm("{ .reg .u64 t; cvta.to.shared.u64 t, %1; cvt.u32.u64 %0, t; }"
        : "=r"(a) : "l"(p));
    return a;
}
__device__ __forceinline__ void cp16(uint32_t dst, const void* src) {
    asm volatile("cp.async.cg.shared.global [%0], [%1], 16;" :: "r"(dst), "l"(src));
}
#define CP_COMMIT()  asm volatile("cp.async.commit_group;" ::: "memory")
#define CP_WAIT(n)   asm volatile("cp.async.wait_group %0;" :: "n"(n) : "memory")

__device__ __forceinline__ void ldsm4(uint32_t a[4], uint32_t addr) {
    asm volatile("ldmatrix.sync.aligned.m8n8.x4.shared.b16 {%0,%1,%2,%3}, [%4];"
        : "=r"(a[0]), "=r"(a[1]), "=r"(a[2]), "=r"(a[3]) : "r"(addr));
}
__device__ __forceinline__ void ldsm2(uint32_t a[2], uint32_t addr) {
    asm volatile("ldmatrix.sync.aligned.m8n8.x2.shared.b16 {%0,%1}, [%2];"
        : "=r"(a[0]), "=r"(a[1]) : "r"(addr));
}
__device__ __forceinline__ void ldsm2t(uint32_t a[2], uint32_t addr) {
    asm volatile("ldmatrix.sync.aligned.m8n8.x2.trans.shared.b16 {%0,%1}, [%2];"
        : "=r"(a[0]), "=r"(a[1]) : "r"(addr));
}
__device__ __forceinline__ void mma_fp(float d[4], const uint32_t a[4], const uint32_t b[2]) {
    asm volatile("mma.sync.aligned.m16n8k16.row.col.f32.f16.f16.f32 "
        "{%0,%1,%2,%3}, {%4,%5,%6,%7}, {%8,%9}, {%0,%1,%2,%3};"
        : "+f"(d[0]), "+f"(d[1]), "+f"(d[2]), "+f"(d[3])
        : "r"(a[0]), "r"(a[1]), "r"(a[2]), "r"(a[3]), "r"(b[0]), "r"(b[1]));
}

// fast exp on FMA pipe (no MUFU)
__device__ __forceinline__ float fexp(float x) {
    float z  = fmaxf(x, -80.f) * 1.4426950408889634f;
    float fz = z + 12582912.f;
    int   n  = __float_as_int(fz) - 0x4B400000;
    float f  = z - (float)n;
    float p  = 1.3333558146428443e-3f;
    p = fmaf(p, f, 9.6181291076284772e-3f);
    p = fmaf(p, f, 5.5504108664821580e-2f);
    p = fmaf(p, f, 2.4022650695910071e-1f);
    p = fmaf(p, f, 6.9314718055994531e-1f);
    p = fmaf(p, f, 1.0f);
    return p * __int_as_float((n + 127) << 23);
}

// ============================================================================
// fp32 -> fp16 conversions, one launch.
// blocks [0,2048): x -> g_xh single; [2048,6144): W (q,k,v single hi; o hi/lo)
// ============================================================================
__global__ __launch_bounds__(256) void conv_all(
    const float* __restrict__ x,  const float* __restrict__ Wq,
    const float* __restrict__ Wk, const float* __restrict__ Wv,
    const float* __restrict__ Wo)
{
    int b = blockIdx.x;
    if (b < 2048) {
        int i = b * 256 + threadIdx.x;
        float4 v = ((const float4*)x)[i];
        __half2* hp = (__half2*)(g_xh + i * 4);
        hp[0] = __floats2half2_rn(v.x, v.y);
        hp[1] = __floats2half2_rn(v.z, v.w);
        return;
    }
    int wsel = (b - 2048) >> 10;
    int off  = (b - 2048) & 1023;
    const float* s = (wsel == 0) ? Wq : (wsel == 1) ? Wk : (wsel == 2) ? Wv : Wo;
    __half* hi = g_wh + (size_t)wsel * (E_ * E_);
    int i = off * 256 + threadIdx.x;
    float4 v = ((const float4*)s)[i];
    __half h0 = __float2half_rn(v.x), h1 = __float2half_rn(v.y);
    __half h2 = __float2half_rn(v.z), h3 = __float2half_rn(v.w);
    __half2* hp = (__half2*)(hi + i * 4);
    hp[0] = __halves2half2(h0, h1); hp[1] = __halves2half2(h2, h3);
    if (wsel == 3) {                  // only Wo keeps a lo correction
        __half l0 = __float2half_rn(v.x - __half2float(h0));
        __half l1 = __float2half_rn(v.y - __half2float(h1));
        __half l2 = __float2half_rn(v.z - __half2float(h2));
        __half l3 = __float2half_rn(v.w - __half2float(h3));
        __half2* lp = (__half2*)(g_wl + (size_t)wsel * (E_ * E_) + i * 4);
        lp[0] = __halves2half2(l0, l1); lp[1] = __halves2half2(l2, l3);
    }
}

// ============================================================================
// fp16 GEMM on mma.sync: C[128,128] = A[M,K] * B[N,K]^T
// mode 0: 1 term (Wh only), x*W[z] -> q/k/v fp16 single in [H][L][64]
// mode 1: 2 terms (Wh+Wl), ao*Wo -> out fp32
// ============================================================================
#define BK    64
#define NCHK  (E_ / BK)
#define TILEB (128 * BK * 2)        // 16 KB per 128xBK fp16 tile
#define STAGEB (3 * TILEB)          // A, Bh, Bl = 48 KB
#define SMEM_MMA (2 * STAGEB)       // 96 KB

__device__ __forceinline__ void load_tile_async(
    uint32_t dst, const __half* src, int row0, int kt, int tid)
{
#pragma unroll
    for (int it = 0; it < 4; it++) {
        int c = tid + it * 256;
        int row = c >> 3;
        int ch  = c & 7;
        const __half* sp = src + (size_t)(row0 + row) * E_ + kt + ch * 8;
        uint32_t sw = row * 128 + ((ch ^ (row & 7)) << 4);
        cp16(dst + sw, sp);
    }
}

__global__ __launch_bounds__(256) void mma_gemm(int mode, float* __restrict__ out)
{
    extern __shared__ char smem[];
    uint32_t sbase = smem_u32(smem);
    int tid  = threadIdx.x;
    int lane = tid & 31;
    int w    = tid >> 5;
    int wm   = w >> 2;
    int wn   = w & 3;
    int z    = blockIdx.z;
    int m0   = blockIdx.y * 128;
    int n0   = blockIdx.x * 128;

    const __half* A = (mode == 0) ? g_xh : g_aoh;
    int wsel = (mode == 0) ? z : 3;
    const __half* Bhi = g_wh + (size_t)wsel * (E_ * E_);
    const __half* Blo = g_wl + (size_t)wsel * (E_ * E_);
    int nt = (mode == 0) ? 1 : 2;

    float acc[4][4][4];
#pragma unroll
    for (int mi = 0; mi < 4; mi++)
#pragma unroll
        for (int ni = 0; ni < 4; ni++)
#pragma unroll
            for (int r = 0; r < 4; r++) acc[mi][ni][r] = 0.f;

    int rl = lane & 7;
    int ai = lane >> 3;
    int aci = ai >> 1;
    int arow[4];
#pragma unroll
    for (int mi = 0; mi < 4; mi++)
        arow[mi] = (wm * 64 + mi * 16 + (ai & 1) * 8 + rl) * 128;
    int bi = (lane >> 3) & 1;
    int brow[4];
#pragma unroll
    for (int ni = 0; ni < 4; ni++)
        brow[ni] = (wn * 32 + ni * 8 + rl) * 128;

    load_tile_async(sbase + 0 * TILEB, A,   m0, 0, tid);
    load_tile_async(sbase + 1 * TILEB, Bhi, n0, 0, tid);
    if (nt == 2) load_tile_async(sbase + 2 * TILEB, Blo, n0, 0, tid);
    CP_COMMIT();

    for (int kt = 0; kt < NCHK; kt++) {
        bool more = (kt + 1) < NCHK;
        if (more) {
            uint32_t nb = sbase + ((kt + 1) & 1) * STAGEB;
            int kk = (kt + 1) * BK;
            load_tile_async(nb + 0 * TILEB, A,   m0, kk, tid);
            load_tile_async(nb + 1 * TILEB, Bhi, n0, kk, tid);
            if (nt == 2) load_tile_async(nb + 2 * TILEB, Blo, n0, kk, tid);
            CP_COMMIT();
            CP_WAIT(1);
        } else {
            CP_WAIT(0);
        }
        __syncthreads();

        uint32_t st = sbase + (kt & 1) * STAGEB;
#pragma unroll
        for (int ks = 0; ks < 4; ks++) {
            uint32_t af[4][4];
            uint32_t choA = (((ks * 2 + aci) ^ rl) << 4);
            uint32_t choB = (((ks * 2 + bi) ^ rl) << 4);
#pragma unroll
            for (int mi = 0; mi < 4; mi++)
                ldsm4(af[mi], st + arow[mi] + choA);
            for (int t = 0; t < nt; t++) {
                uint32_t uB = st + TILEB + t * TILEB;
                uint32_t bf[4][2];
#pragma unroll
                for (int ni = 0; ni < 4; ni++)
                    ldsm2(bf[ni], uB + brow[ni] + choB);
#pragma unroll
                for (int mi = 0; mi < 4; mi++)
#pragma unroll
                    for (int ni = 0; ni < 4; ni++)
                        mma_fp(acc[mi][ni], af[mi], bf[ni]);
            }
        }
        __syncthreads();
    }

    int mrow = m0 + wm * 64 + (lane >> 2);
    int ncol = n0 + wn * 32 + (lane & 3) * 2;
#pragma unroll
    for (int mi = 0; mi < 4; mi++) {
#pragma unroll
        for (int ni = 0; ni < 4; ni++) {
            int n = ncol + ni * 8;
#pragma unroll
            for (int half = 0; half < 2; half++) {
                int m = mrow + mi * 16 + half * 8;
                float v0 = acc[mi][ni][half * 2], v1 = acc[mi][ni][half * 2 + 1];
                if (mode == 0) {
                    size_t o = ((size_t)(n >> 6) * L_ + m) * 64 + (n & 63);
                    __half* C = (z == 0) ? g_qh : (z == 1) ? g_kh : g_vh;
                    *(__half2*)(C + o) = __floats2half2_rn(v0, v1);
                } else {
                    *(float2*)(out + (size_t)m * E_ + n) = make_float2(v0, v1);
                }
            }
        }
    }
}

// ============================================================================
// Attention. CTA (p, h): 64-row q-tiles {31-p, p}.
// Pass 1: S = q*k fp16 mma (1 term), e = fexp(s*scale+bias) -> g_e fp16, Z.
// Pass 2: t = relu(e*invZ + tau/idx) fp16 -> smem; O += T*V; O -> g_aoh fp16.
// ============================================================================
#define AT_    0u          /* 8 KB: Q (pass1) / T (pass2) */
#define AKV_   8192u       /* 2 bufs x 8 KB (K in pass1, V in pass2) */
#define ABIAS_ 24576u      /* 8 KB */
#define AZP_   32768u      /* 2 x 64 floats */
#define AINVZ_ 33280u
#define ATAUT_ 33536u
#define SMEM_ATT 33792

__global__ __launch_bounds__(256) void attn_kernel(
    const float* __restrict__ bias, const float* __restrict__ tau)
{
    extern __shared__ char smem[];
    uint32_t sb = smem_u32(smem);
    float* sbias = (float*)(smem + ABIAS_);
    float* szp   = (float*)(smem + AZP_);
    float* sinvz = (float*)(smem + AINVZ_);
    float* staut = (float*)(smem + ATAUT_);

    int h   = blockIdx.y;
    int p   = blockIdx.x;           // 0..15
    int tid = threadIdx.x;
    int lane = tid & 31, w = tid >> 5;
    int wm = w >> 1, wn = w & 1;    // 4 m-warps x 2 n-warps
    int rl = lane & 7;
    int ai = lane >> 3, aci = ai >> 1, bi = ai & 1;
    float tauh = tau[h];
    const float scale = 0.125f;

    for (int i = tid; i < MBL_ / 4; i += 256)
        *(float4*)&sbias[i * 4] = *(const float4*)&bias[h * MBL_ + i * 4];

    const __half* qh = g_qh + (size_t)h * (L_ * 64);
    const __half* kh = g_kh + (size_t)h * (L_ * 64);
    const __half* vh = g_vh + (size_t)h * (L_ * 64);
    __half* eh = g_e + (size_t)h * L_ * L_;

    uint32_t arow = (uint32_t)((wm * 16 + (ai & 1) * 8 + rl) * 128);
    uint32_t brow[4];
#pragma unroll
    for (int ni = 0; ni < 4; ni++)
        brow[ni] = (uint32_t)((wn * 32 + ni * 8 + rl) * 128);

    for (int which = 0; which < 2; which++) {
        int iq = which ? p : (31 - p);
        int q0 = iq * 64;
        int nch = iq + 1;

        __syncthreads();            // previous tile fully done with smem

        // ---- load Q (fp16, 64 rows x 128B) + K chunk 0 ----
#pragma unroll
        for (int it = 0; it < 2; it++) {
            int c = tid + it * 256;
            int row = c >> 3, ch = c & 7;
            uint32_t sw = row * 128 + ((ch ^ (row & 7)) << 4);
            cp16(sb + AT_ + sw, qh + (size_t)(q0 + row) * 64 + ch * 8);
            cp16(sb + AKV_ + sw, kh + (size_t)row * 64 + ch * 8);
        }
        CP_COMMIT();

        float rs[2] = {0.f, 0.f};

        // ==================== PASS 1 ====================
        for (int j = 0; j < nch; j++) {
            int b = j & 1;
            int k0 = j * 64;
            if (j + 1 < nch) {
                uint32_t nb = sb + AKV_ + (b ^ 1) * 8192;
                int k0n = (j + 1) * 64;
#pragma unroll
                for (int it = 0; it < 2; it++) {
                    int c = tid + it * 256;
                    int row = c >> 3, ch = c & 7;
                    uint32_t sw = row * 128 + ((ch ^ (row & 7)) << 4);
                    cp16(nb + sw, kh + (size_t)(k0n + row) * 64 + ch * 8);
                }
                CP_COMMIT();
                CP_WAIT(1);
            } else {
                CP_WAIT(0);
            }
            __syncthreads();

            float sacc[4][4];
#pragma unroll
            for (int ni = 0; ni < 4; ni++)
#pragma unroll
                for (int r = 0; r < 4; r++) sacc[ni][r] = 0.f;

            uint32_t bkh = sb + AKV_ + b * 8192;
#pragma unroll
            for (int ks = 0; ks < 4; ks++) {
                uint32_t qf[4], khf[4][2];
                uint32_t choA = (((ks * 2 + aci) ^ rl) << 4);
                uint32_t choB = (((ks * 2 + bi) ^ rl) << 4);
                ldsm4(qf, sb + AT_ + arow + choA);
#pragma unroll
                for (int ni = 0; ni < 4; ni++)
                    ldsm2(khf[ni], bkh + brow[ni] + choB);
#pragma unroll
                for (int ni = 0; ni < 4; ni++)
                    mma_fp(sacc[ni], qf, khf[ni]);
            }
            __syncthreads();    // K buf b reusable

            // epilogue: scale + bias + causal, exp, store e, Z partials
            int r = wm * 16 + (lane >> 2);
#pragma unroll
            for (int ni = 0; ni < 4; ni++) {
                int kk = k0 + wn * 32 + ni * 8 + (lane & 3) * 2;
#pragma unroll
                for (int hh = 0; hh < 2; hh++) {
                    int qq = q0 + r + hh * 8;
                    float s0 = sacc[ni][hh * 2]     * scale;
                    float s1 = sacc[ni][hh * 2 + 1] * scale;
                    int d0 = qq - kk, d1 = d0 - 1;
                    float e0 = (d0 >= 0) ? fexp(s0 + sbias[d0]) : 0.f;
                    float e1 = (d1 >= 0) ? fexp(s1 + sbias[d1]) : 0.f;
                    *(__half2*)(eh + (size_t)qq * L_ + kk) = __floats2half2_rn(e0, e1);
                    rs[hh] += e0 + e1;
                }
            }
        }

        // ---- finalize Z ----
#pragma unroll
        for (int hh = 0; hh < 2; hh++) {
            rs[hh] += __shfl_xor_sync(0xffffffffu, rs[hh], 1);
            rs[hh] += __shfl_xor_sync(0xffffffffu, rs[hh], 2);
        }
        if ((lane & 3) == 0) {
            int r0 = wm * 16 + (lane >> 2);
            szp[wn * 64 + r0]     = rs[0];
            szp[wn * 64 + r0 + 8] = rs[1];
        }
        __syncthreads();
        if (tid < 64) {
            float Zr = szp[tid] + szp[64 + tid];
            sinvz[tid] = 1.f / Zr;
            staut[tid] = tauh / (float)(q0 + tid + 1);
        }
        // prefetch V chunk 0 into buf 0
#pragma unroll
        for (int it = 0; it < 2; it++) {
            int c = tid + it * 256;
            int row = c >> 3, ch = c & 7;
            uint32_t sw = row * 128 + ((ch ^ (row & 7)) << 4);
            cp16(sb + AKV_ + sw, vh + (size_t)row * 64 + ch * 8);
        }
        CP_COMMIT();
        __syncthreads();

        // ==================== PASS 2 ====================
        float oacc[4][4];
#pragma unroll
        for (int ni = 0; ni < 4; ni++)
#pragma unroll
            for (int r = 0; r < 4; r++) oacc[ni][r] = 0.f;

        for (int j = 0; j < nch; j++) {
            int b = j & 1;
            int k0 = j * 64;
            // build T tile (fp16) in AT_ (prev chunk's MMA done: trailing sync)
#pragma unroll
            for (int it = 0; it < 2; it++) {
                int c = tid + it * 256;
                int row = c >> 3, ch = c & 7;
                uint4 ev = *(const uint4*)(eh + (size_t)(q0 + row) * L_ + k0 + ch * 8);
                float iz = sinvz[row], tt = staut[row];
                const __half2* ep = (const __half2*)&ev;
                uint32_t tw[4];
#pragma unroll
                for (int u = 0; u < 4; u++) {
                    float2 e2 = __half22float2(ep[u]);
                    float t0 = fmaxf(fmaf(e2.x, iz, tt), 0.f);
                    float t1 = fmaxf(fmaf(e2.y, iz, tt), 0.f);
                    __half2 tp = __floats2half2_rn(t0, t1);
                    tw[u] = *(uint32_t*)&tp;
                }
                uint32_t sw = row * 128 + ((ch ^ (row & 7)) << 4);
                *(uint4*)(smem + AT_ + sw) = make_uint4(tw[0], tw[1], tw[2], tw[3]);
            }
            if (j + 1 < nch) {
                uint32_t nb = sb + AKV_ + (b ^ 1) * 8192;
                int k0n = (j + 1) * 64;
#pragma unroll
                for (int it = 0; it < 2; it++) {
                    int c = tid + it * 256;
                    int row = c >> 3, ch = c & 7;
                    uint32_t sw = row * 128 + ((ch ^ (row & 7)) << 4);
                    cp16(nb + sw, vh + (size_t)(k0n + row) * 64 + ch * 8);
                }
                CP_COMMIT();
                CP_WAIT(1);
            } else {
                CP_WAIT(0);
            }
            __syncthreads();

            uint32_t bv = sb + AKV_ + b * 8192;
            int krl = lane & 15;
#pragma unroll
            for (int ks = 0; ks < 4; ks++) {
                uint32_t tf[4], vf[4][2];
                uint32_t choA = (((ks * 2 + aci) ^ rl) << 4);
                ldsm4(tf, sb + AT_ + arow + choA);
                int kr = ks * 16 + krl;
#pragma unroll
                for (int ni = 0; ni < 4; ni++) {
                    uint32_t off = kr * 128 + (((wn * 4 + ni) ^ (kr & 7)) << 4);
                    ldsm2t(vf[ni], bv + off);
                }
#pragma unroll
                for (int ni = 0; ni < 4; ni++)
                    mma_fp(oacc[ni], tf, vf[ni]);
            }
            __syncthreads();    // T + V buf free for next chunk
        }

        // ---- O -> g_aoh fp16 ----
#pragma unroll
        for (int ni = 0; ni < 4; ni++) {
            int c = wn * 32 + ni * 8 + (lane & 3) * 2;
#pragma unroll
            for (int hh = 0; hh < 2; hh++) {
                int q = q0 + wm * 16 + (lane >> 2) + hh * 8;
                float v0 = oacc[ni][hh * 2], v1 = oacc[ni][hh * 2 + 1];
                size_t o = (size_t)q * E_ + h * 64 + c;
                *(__half2*)(g_aoh + o) = __floats2half2_rn(v0, v1);
            }
        }
    }
}

// ============================================================================
extern "C" void kernel_launch(void* const* d_in, const int* in_sizes, int n_in,
                              void* d_out, int out_size)
{
    (void)in_sizes; (void)n_in; (void)out_size;
    const float* x    = (const float*)d_in[0];
    const float* Wq   = (const float*)d_in[1];
    const float* Wk   = (const float*)d_in[2];
    const float* Wv   = (const float*)d_in[3];
    const float* Wo   = (const float*)d_in[4];
    const float* bias = (const float*)d_in[5];
    const float* tau  = (const float*)d_in[6];
    float* out = (float*)d_out;

    cudaFuncSetAttribute(mma_gemm, cudaFuncAttributeMaxDynamicSharedMemorySize, SMEM_MMA);
    cudaFuncSetAttribute(attn_kernel, cudaFuncAttributeMaxDynamicSharedMemorySize, SMEM_ATT);

    conv_all<<<2048 + 4 * 1024, 256>>>(x, Wq, Wk, Wv, Wo);
    mma_gemm<<<dim3(E_ / 128, L_ / 128, 3), 256, SMEM_MMA>>>(0, nullptr);
    attn_kernel<<<dim3(16, H_), 256, SMEM_ATT>>>(bias, tau);
    mma_gemm<<<dim3(E_ / 128, L_ / 128, 1), 256, SMEM_MMA>>>(1, out);
}

// round 13
// speedup vs baseline: 1.2956x; 1.0231x over previous
#include <cuda_runtime.h>
#include <cuda_bf16.h>
#include <cuda_fp16.h>
#include <cstdint>
#include <math.h>

#define L_   2048
#define E_   1024
#define H_   16
#define D_   64
#define MBL_ 2048

// ---------------- device scratch (static; allocation-free) -----------------
__device__ __half g_e[(size_t)H_ * L_ * L_];    // exp(s), unnormalized, fp16

// fp16 operands for the big GEMMs
__device__ __half g_xh[L_ * E_];
__device__ __half g_wh[4 * E_ * E_], g_wl[4 * E_ * E_];   // lo used for Wo only
__device__ __half g_aoh[L_ * E_];
// fp16 attention operands, [H][L][64] (all single-rounded)
__device__ __half g_qh[H_ * L_ * D_];
__device__ __half g_kh[H_ * L_ * D_];
__device__ __half g_vh[H_ * L_ * D_];

// ============================ PTX helpers (sm_80+) ==========================
__device__ __forceinline__ uint32_t smem_u32(const void* p) {
    uint32_t a;
    asm("{ .reg .u64 t; cvta.to.shared.u64 t, %1; cvt.u32.u64 %0, t; }"
        : "=r"(a) : "l"(p));
    return a;
}
__device__ __forceinline__ void cp16(uint32_t dst, const void* src) {
    asm volatile("cp.async.cg.shared.global [%0], [%1], 16;" :: "r"(dst), "l"(src));
}
#define CP_COMMIT()  asm volatile("cp.async.commit_group;" ::: "memory")
#define CP_WAIT(n)   asm volatile("cp.async.wait_group %0;" :: "n"(n) : "memory")

__device__ __forceinline__ void ldsm4(uint32_t a[4], uint32_t addr) {
    asm volatile("ldmatrix.sync.aligned.m8n8.x4.shared.b16 {%0,%1,%2,%3}, [%4];"
        : "=r"(a[0]), "=r"(a[1]), "=r"(a[2]), "=r"(a[3]) : "r"(addr));
}
__device__ __forceinline__ void ldsm2(uint32_t a[2], uint32_t addr) {
    asm volatile("ldmatrix.sync.aligned.m8n8.x2.shared.b16 {%0,%1}, [%2];"
        : "=r"(a[0]), "=r"(a[1]) : "r"(addr));
}
__device__ __forceinline__ void ldsm2t(uint32_t a[2], uint32_t addr) {
    asm volatile("ldmatrix.sync.aligned.m8n8.x2.trans.shared.b16 {%0,%1}, [%2];"
        : "=r"(a[0]), "=r"(a[1]) : "r"(addr));
}
__device__ __forceinline__ void mma_fp(float d[4], const uint32_t a[4], const uint32_t b[2]) {
    asm volatile("mma.sync.aligned.m16n8k16.row.col.f32.f16.f16.f32 "
        "{%0,%1,%2,%3}, {%4,%5,%6,%7}, {%8,%9}, {%0,%1,%2,%3};"
        : "+f"(d[0]), "+f"(d[1]), "+f"(d[2]), "+f"(d[3])
        : "r"(a[0]), "r"(a[1]), "r"(a[2]), "r"(a[3]), "r"(b[0]), "r"(b[1]));
}

// fast exp on FMA pipe (no MUFU)
__device__ __forceinline__ float fexp(float x) {
    float z  = fmaxf(x, -80.f) * 1.4426950408889634f;
    float fz = z + 12582912.f;
    int   n  = __float_as_int(fz) - 0x4B400000;
    float f  = z - (float)n;
    float p  = 1.3333558146428443e-3f;
    p = fmaf(p, f, 9.6181291076284772e-3f);
    p = fmaf(p, f, 5.5504108664821580e-2f);
    p = fmaf(p, f, 2.4022650695910071e-1f);
    p = fmaf(p, f, 6.9314718055994531e-1f);
    p = fmaf(p, f, 1.0f);
    return p * __int_as_float((n + 127) << 23);
}

// ============================================================================
// fp32 -> fp16 conversions, one launch.
// ============================================================================
__global__ __launch_bounds__(256) void conv_all(
    const float* __restrict__ x,  const float* __restrict__ Wq,
    const float* __restrict__ Wk, const float* __restrict__ Wv,
    const float* __restrict__ Wo)
{
    int b = blockIdx.x;
    if (b < 2048) {
        int i = b * 256 + threadIdx.x;
        float4 v = ((const float4*)x)[i];
        __half2* hp = (__half2*)(g_xh + i * 4);
        hp[0] = __floats2half2_rn(v.x, v.y);
        hp[1] = __floats2half2_rn(v.z, v.w);
        return;
    }
    int wsel = (b - 2048) >> 10;
    int off  = (b - 2048) & 1023;
    const float* s = (wsel == 0) ? Wq : (wsel == 1) ? Wk : (wsel == 2) ? Wv : Wo;
    __half* hi = g_wh + (size_t)wsel * (E_ * E_);
    int i = off * 256 + threadIdx.x;
    float4 v = ((const float4*)s)[i];
    __half h0 = __float2half_rn(v.x), h1 = __float2half_rn(v.y);
    __half h2 = __float2half_rn(v.z), h3 = __float2half_rn(v.w);
    __half2* hp = (__half2*)(hi + i * 4);
    hp[0] = __halves2half2(h0, h1); hp[1] = __halves2half2(h2, h3);
    if (wsel == 3) {                  // only Wo keeps a lo correction
        __half l0 = __float2half_rn(v.x - __half2float(h0));
        __half l1 = __float2half_rn(v.y - __half2float(h1));
        __half l2 = __float2half_rn(v.z - __half2float(h2));
        __half l3 = __float2half_rn(v.w - __half2float(h3));
        __half2* lp = (__half2*)(g_wl + (size_t)wsel * (E_ * E_) + i * 4);
        lp[0] = __halves2half2(l0, l1); lp[1] = __halves2half2(l2, l3);
    }
}

// ============================================================================
// fp16 GEMM on mma.sync: C[128,128] = A[M,K] * B[N,K]^T  (unchanged, frozen)
// mode 0: 1 term (Wh only), x*W[z] -> q/k/v fp16 single in [H][L][64]
// mode 1: 2 terms (Wh+Wl), ao*Wo -> out fp32
// ============================================================================
#define BK    64
#define NCHK  (E_ / BK)
#define TILEB (128 * BK * 2)
#define STAGEB (3 * TILEB)
#define SMEM_MMA (2 * STAGEB)

__device__ __forceinline__ void load_tile_async(
    uint32_t dst, const __half* src, int row0, int kt, int tid)
{
#pragma unroll
    for (int it = 0; it < 4; it++) {
        int c = tid + it * 256;
        int row = c >> 3;
        int ch  = c & 7;
        const __half* sp = src + (size_t)(row0 + row) * E_ + kt + ch * 8;
        uint32_t sw = row * 128 + ((ch ^ (row & 7)) << 4);
        cp16(dst + sw, sp);
    }
}

__global__ __launch_bounds__(256) void mma_gemm(int mode, float* __restrict__ out)
{
    extern __shared__ char smem[];
    uint32_t sbase = smem_u32(smem);
    int tid  = threadIdx.x;
    int lane = tid & 31;
    int w    = tid >> 5;
    int wm   = w >> 2;
    int wn   = w & 3;
    int z    = blockIdx.z;
    int m0   = blockIdx.y * 128;
    int n0   = blockIdx.x * 128;

    const __half* A = (mode == 0) ? g_xh : g_aoh;
    int wsel = (mode == 0) ? z : 3;
    const __half* Bhi = g_wh + (size_t)wsel * (E_ * E_);
    const __half* Blo = g_wl + (size_t)wsel * (E_ * E_);
    int nt = (mode == 0) ? 1 : 2;

    float acc[4][4][4];
#pragma unroll
    for (int mi = 0; mi < 4; mi++)
#pragma unroll
        for (int ni = 0; ni < 4; ni++)
#pragma unroll
            for (int r = 0; r < 4; r++) acc[mi][ni][r] = 0.f;

    int rl = lane & 7;
    int ai = lane >> 3;
    int aci = ai >> 1;
    int arow[4];
#pragma unroll
    for (int mi = 0; mi < 4; mi++)
        arow[mi] = (wm * 64 + mi * 16 + (ai & 1) * 8 + rl) * 128;
    int bi = (lane >> 3) & 1;
    int brow[4];
#pragma unroll
    for (int ni = 0; ni < 4; ni++)
        brow[ni] = (wn * 32 + ni * 8 + rl) * 128;

    load_tile_async(sbase + 0 * TILEB, A,   m0, 0, tid);
    load_tile_async(sbase + 1 * TILEB, Bhi, n0, 0, tid);
    if (nt == 2) load_tile_async(sbase + 2 * TILEB, Blo, n0, 0, tid);
    CP_COMMIT();

    for (int kt = 0; kt < NCHK; kt++) {
        bool more = (kt + 1) < NCHK;
        if (more) {
            uint32_t nb = sbase + ((kt + 1) & 1) * STAGEB;
            int kk = (kt + 1) * BK;
            load_tile_async(nb + 0 * TILEB, A,   m0, kk, tid);
            load_tile_async(nb + 1 * TILEB, Bhi, n0, kk, tid);
            if (nt == 2) load_tile_async(nb + 2 * TILEB, Blo, n0, kk, tid);
            CP_COMMIT();
            CP_WAIT(1);
        } else {
            CP_WAIT(0);
        }
        __syncthreads();

        uint32_t st = sbase + (kt & 1) * STAGEB;
#pragma unroll
        for (int ks = 0; ks < 4; ks++) {
            uint32_t af[4][4];
            uint32_t choA = (((ks * 2 + aci) ^ rl) << 4);
            uint32_t choB = (((ks * 2 + bi) ^ rl) << 4);
#pragma unroll
            for (int mi = 0; mi < 4; mi++)
                ldsm4(af[mi], st + arow[mi] + choA);
            for (int t = 0; t < nt; t++) {
                uint32_t uB = st + TILEB + t * TILEB;
                uint32_t bf[4][2];
#pragma unroll
                for (int ni = 0; ni < 4; ni++)
                    ldsm2(bf[ni], uB + brow[ni] + choB);
#pragma unroll
                for (int mi = 0; mi < 4; mi++)
#pragma unroll
                    for (int ni = 0; ni < 4; ni++)
                        mma_fp(acc[mi][ni], af[mi], bf[ni]);
            }
        }
        __syncthreads();
    }

    int mrow = m0 + wm * 64 + (lane >> 2);
    int ncol = n0 + wn * 32 + (lane & 3) * 2;
#pragma unroll
    for (int mi = 0; mi < 4; mi++) {
#pragma unroll
        for (int ni = 0; ni < 4; ni++) {
            int n = ncol + ni * 8;
#pragma unroll
            for (int half = 0; half < 2; half++) {
                int m = mrow + mi * 16 + half * 8;
                float v0 = acc[mi][ni][half * 2], v1 = acc[mi][ni][half * 2 + 1];
                if (mode == 0) {
                    size_t o = ((size_t)(n >> 6) * L_ + m) * 64 + (n & 63);
                    __half* C = (z == 0) ? g_qh : (z == 1) ? g_kh : g_vh;
                    *(__half2*)(C + o) = __floats2half2_rn(v0, v1);
                } else {
                    *(float2*)(out + (size_t)m * E_ + n) = make_float2(v0, v1);
                }
            }
        }
    }
}

// ============================================================================
// Attention. Grid 512 = 32 q-tiles (heavy first) x 16 heads; 64-row q-tiles.
// 256 thr = 8 warps: 4 m-warps x 2 n-warps. BK=128 k-chunks.
// Pass 1: S = q*k fp16 mma, e = fexp(s*scale+bias) -> g_e fp16, Z sums.
// Pass 2: t = relu(e*invZ + tau/idx) fp16 -> smem (two 64-col sub-tiles);
//         O += T*V; O -> g_aoh fp16.
// Masked (k>q) positions give e=0 -> t=relu(tau/idx)=0 (tau<0), so 128-chunk
// over-reads past the causal edge are harmless.
// ============================================================================
#define AT0_   0u          /* 8 KB: Q (pass1) / T cols 0..63 (pass2) */
#define AT1_   8192u       /* 8 KB: T cols 64..127 (pass2) */
#define AKV_   16384u      /* 2 bufs x 16 KB (K 128 rows in pass1, V in pass2) */
#define ABIAS_ 49152u      /* 8 KB */
#define AZP_   57344u      /* 2 x 64 floats */
#define AINVZ_ 57856u
#define ATAUT_ 58112u
#define SMEM_ATT 58368

__global__ __launch_bounds__(256) void attn_kernel(
    const float* __restrict__ bias, const float* __restrict__ tau)
{
    extern __shared__ char smem[];
    uint32_t sb = smem_u32(smem);
    float* sbias = (float*)(smem + ABIAS_);
    float* szp   = (float*)(smem + AZP_);
    float* sinvz = (float*)(smem + AINVZ_);
    float* staut = (float*)(smem + ATAUT_);

    int bx  = blockIdx.x;
    int iq  = 31 - (bx >> 4);       // heavy q-tiles first
    int h   = bx & 15;
    int q0  = iq * 64;
    int nch = (q0 + 64 + 127) >> 7; // 128-row k-chunks covering [0, q0+64)

    int tid = threadIdx.x;
    int lane = tid & 31, w = tid >> 5;
    int wm = w >> 1, wn = w & 1;    // 4 m-warps x 2 n-warps
    int rl = lane & 7;
    int ai = lane >> 3, aci = ai >> 1, bi = ai & 1;
    float tauh = tau[h];
    const float scale = 0.125f;

    for (int i = tid; i < MBL_ / 4; i += 256)
        *(float4*)&sbias[i * 4] = *(const float4*)&bias[h * MBL_ + i * 4];

    const __half* qh = g_qh + (size_t)h * (L_ * 64);
    const __half* kh = g_kh + (size_t)h * (L_ * 64);
    const __half* vh = g_vh + (size_t)h * (L_ * 64);
    __half* eh = g_e + (size_t)h * L_ * L_;

    uint32_t arow = (uint32_t)((wm * 16 + (ai & 1) * 8 + rl) * 128);
    uint32_t brow8[8];
#pragma unroll
    for (int ni = 0; ni < 8; ni++)
        brow8[ni] = (uint32_t)((wn * 64 + ni * 8 + rl) * 128);
    uint32_t brow4[4];
#pragma unroll
    for (int ni = 0; ni < 4; ni++)
        brow4[ni] = (uint32_t)((wn * 32 + ni * 8 + rl) * 128);

    // ---- load Q (64 rows x 128B) + K chunk 0 (128 rows x 128B) ----
#pragma unroll
    for (int it = 0; it < 2; it++) {
        int c = tid + it * 256;
        int row = c >> 3, ch = c & 7;
        uint32_t sw = row * 128 + ((ch ^ (row & 7)) << 4);
        cp16(sb + AT0_ + sw, qh + (size_t)(q0 + row) * 64 + ch * 8);
    }
#pragma unroll
    for (int it = 0; it < 4; it++) {
        int c = tid + it * 256;
        int row = c >> 3, ch = c & 7;
        uint32_t sw = row * 128 + ((ch ^ (row & 7)) << 4);
        cp16(sb + AKV_ + sw, kh + (size_t)row * 64 + ch * 8);
    }
    CP_COMMIT();

    float rs[2] = {0.f, 0.f};

    // ==================== PASS 1 ====================
    for (int j = 0; j < nch; j++) {
        int b = j & 1;
        int k0 = j * 128;
        if (j + 1 < nch) {
            uint32_t nb = sb + AKV_ + (b ^ 1) * 16384;
            int k0n = (j + 1) * 128;
#pragma unroll
            for (int it = 0; it < 4; it++) {
                int c = tid + it * 256;
                int row = c >> 3, ch = c & 7;
                uint32_t sw = row * 128 + ((ch ^ (row & 7)) << 4);
                cp16(nb + sw, kh + (size_t)(k0n + row) * 64 + ch * 8);
            }
            CP_COMMIT();
            CP_WAIT(1);
        } else {
            CP_WAIT(0);
        }
        __syncthreads();

        float sacc[8][4];
#pragma unroll
        for (int ni = 0; ni < 8; ni++)
#pragma unroll
            for (int r = 0; r < 4; r++) sacc[ni][r] = 0.f;

        uint32_t bkh = sb + AKV_ + b * 16384;
#pragma unroll
        for (int ks = 0; ks < 4; ks++) {
            uint32_t qf[4];
            uint32_t choA = (((ks * 2 + aci) ^ rl) << 4);
            uint32_t choB = (((ks * 2 + bi) ^ rl) << 4);
            ldsm4(qf, sb + AT0_ + arow + choA);
#pragma unroll
            for (int ni = 0; ni < 8; ni++) {
                uint32_t kf[2];
                ldsm2(kf, bkh + brow8[ni] + choB);
                mma_fp(sacc[ni], qf, kf);
            }
        }
        __syncthreads();    // K buf b reusable

        // epilogue: scale + bias + causal, exp, store e, Z partials
        int r = wm * 16 + (lane >> 2);
#pragma unroll
        for (int ni = 0; ni < 8; ni++) {
            int kk = k0 + wn * 64 + ni * 8 + (lane & 3) * 2;
#pragma unroll
            for (int hh = 0; hh < 2; hh++) {
                int qq = q0 + r + hh * 8;
                float s0 = sacc[ni][hh * 2]     * scale;
                float s1 = sacc[ni][hh * 2 + 1] * scale;
                int d0 = qq - kk, d1 = d0 - 1;
                float e0 = (d0 >= 0) ? fexp(s0 + sbias[d0]) : 0.f;
                float e1 = (d1 >= 0) ? fexp(s1 + sbias[d1]) : 0.f;
                *(__half2*)(eh + (size_t)qq * L_ + kk) = __floats2half2_rn(e0, e1);
                rs[hh] += e0 + e1;
            }
        }
    }

    // ---- finalize Z ----
#pragma unroll
    for (int hh = 0; hh < 2; hh++) {
        rs[hh] += __shfl_xor_sync(0xffffffffu, rs[hh], 1);
        rs[hh] += __shfl_xor_sync(0xffffffffu, rs[hh], 2);
    }
    if ((lane & 3) == 0) {
        int r0 = wm * 16 + (lane >> 2);
        szp[wn * 64 + r0]     = rs[0];
        szp[wn * 64 + r0 + 8] = rs[1];
    }
    __syncthreads();
    if (tid < 64) {
        float Zr = szp[tid] + szp[64 + tid];
        sinvz[tid] = 1.f / Zr;
        staut[tid] = tauh / (float)(q0 + tid + 1);
    }
    // prefetch V chunk 0 into buf 0
#pragma unroll
    for (int it = 0; it < 4; it++) {
        int c = tid + it * 256;
        int row = c >> 3, ch = c & 7;
        uint32_t sw = row * 128 + ((ch ^ (row & 7)) << 4);
        cp16(sb + AKV_ + sw, vh + (size_t)row * 64 + ch * 8);
    }
    CP_COMMIT();
    __syncthreads();

    // ==================== PASS 2 ====================
    float oacc[4][4];
#pragma unroll
    for (int ni = 0; ni < 4; ni++)
#pragma unroll
        for (int r = 0; r < 4; r++) oacc[ni][r] = 0.f;

    for (int j = 0; j < nch; j++) {
        int b = j & 1;
        int k0 = j * 128;
        // build T tiles (fp16, two 64-col sub-tiles) in AT0_/AT1_
#pragma unroll
        for (int it = 0; it < 4; it++) {
            int c = tid + it * 256;
            int row = c >> 4, ch = c & 15;       // 64 rows x 16 chunks of 8
            uint4 ev = *(const uint4*)(eh + (size_t)(q0 + row) * L_ + k0 + ch * 8);
            float iz = sinvz[row], tt = staut[row];
            const __half2* ep = (const __half2*)&ev;
            uint32_t tw[4];
#pragma unroll
            for (int u = 0; u < 4; u++) {
                float2 e2 = __half22float2(ep[u]);
                float t0 = fmaxf(fmaf(e2.x, iz, tt), 0.f);
                float t1 = fmaxf(fmaf(e2.y, iz, tt), 0.f);
                __half2 tp = __floats2half2_rn(t0, t1);
                tw[u] = *(uint32_t*)&tp;
            }
            int sub = ch >> 3;                   // 0: cols 0..63, 1: 64..127
            int lch = ch & 7;
            uint32_t sw = row * 128 + ((lch ^ (row & 7)) << 4);
            *(uint4*)(smem + (sub ? AT1_ : AT0_) + sw) = make_uint4(tw[0], tw[1], tw[2], tw[3]);
        }
        if (j + 1 < nch) {
            uint32_t nb = sb + AKV_ + (b ^ 1) * 16384;
            int k0n = (j + 1) * 128;
#pragma unroll
            for (int it = 0; it < 4; it++) {
                int c = tid + it * 256;
                int row = c >> 3, ch = c & 7;
                uint32_t sw = row * 128 + ((ch ^ (row & 7)) << 4);
                cp16(nb + sw, vh + (size_t)(k0n + row) * 64 + ch * 8);
            }
            CP_COMMIT();
            CP_WAIT(1);
        } else {
            CP_WAIT(0);
        }
        __syncthreads();

        uint32_t bv = sb + AKV_ + b * 16384;
        int krl = lane & 15;
#pragma unroll
        for (int ks = 0; ks < 8; ks++) {
            int lks = ks & 3;
            uint32_t tbase = (ks < 4) ? AT0_ : AT1_;
            uint32_t tf[4], vf[4][2];
            uint32_t choA = (((lks * 2 + aci) ^ rl) << 4);
            ldsm4(tf, sb + tbase + arow + choA);
            int kr = ks * 16 + krl;              // 0..127 V rows
#pragma unroll
            for (int ni = 0; ni < 4; ni++) {
                uint32_t off = kr * 128 + (((wn * 4 + ni) ^ (kr & 7)) << 4);
                ldsm2t(vf[ni], bv + off);
            }
#pragma unroll
            for (int ni = 0; ni < 4; ni++)
                mma_fp(oacc[ni], tf, vf[ni]);
        }
        __syncthreads();    // T + V buf free for next chunk
    }

    // ---- O -> g_aoh fp16 ----
#pragma unroll
    for (int ni = 0; ni < 4; ni++) {
        int c = wn * 32 + ni * 8 + (lane & 3) * 2;
#pragma unroll
        for (int hh = 0; hh < 2; hh++) {
            int q = q0 + wm * 16 + (lane >> 2) + hh * 8;
            float v0 = oacc[ni][hh * 2], v1 = oacc[ni][hh * 2 + 1];
            size_t o = (size_t)q * E_ + h * 64 + c;
            *(__half2*)(g_aoh + o) = __floats2half2_rn(v0, v1);
        }
    }
}

// ============================================================================
extern "C" void kernel_launch(void* const* d_in, const int* in_sizes, int n_in,
                              void* d_out, int out_size)
{
    (void)in_sizes; (void)n_in; (void)out_size;
    const float* x    = (const float*)d_in[0];
    const float* Wq   = (const float*)d_in[1];
    const float* Wk   = (const float*)d_in[2];
    const float* Wv   = (const float*)d_in[3];
    const float* Wo   = (const float*)d_in[4];
    const float* bias = (const float*)d_in[5];
    const float* tau  = (const float*)d_in[6];
    float* out = (float*)d_out;

    cudaFuncSetAttribute(mma_gemm, cudaFuncAttributeMaxDynamicSharedMemorySize, SMEM_MMA);
    cudaFuncSetAttribute(attn_kernel, cudaFuncAttributeMaxDynamicSharedMemorySize, SMEM_ATT);

    conv_all<<<2048 + 4 * 1024, 256>>>(x, Wq, Wk, Wv, Wo);
    mma_gemm<<<dim3(E_ / 128, L_ / 128, 3), 256, SMEM_MMA>>>(0, nullptr);
    attn_kernel<<<512, 256, SMEM_ATT>>>(bias, tau);
    mma_gemm<<<dim3(E_ / 128, L_ / 128, 1), 256, SMEM_MMA>>>(1, out);
}

// round 14
// speedup vs baseline: 1.4388x; 1.1105x over previous
#include <cuda_runtime.h>
#include <cuda_bf16.h>
#include <cuda_fp16.h>
#include <cstdint>
#include <math.h>

#define L_   2048
#define E_   1024
#define H_   16
#define D_   64
#define MBL_ 2048

// ---------------- device scratch (static; allocation-free) -----------------
__device__ __half g_e[(size_t)H_ * L_ * L_];    // exp(s), unnormalized, fp16

// fp16 operands for the big GEMMs
__device__ __half g_xh[L_ * E_];
__device__ __half g_wh[4 * E_ * E_], g_wl[4 * E_ * E_];   // lo used for Wo only
__device__ __half g_aoh[L_ * E_];
// fp16 attention operands, [H][L][64] (all single-rounded)
__device__ __half g_qh[H_ * L_ * D_];
__device__ __half g_kh[H_ * L_ * D_];
__device__ __half g_vh[H_ * L_ * D_];

// ============================ PTX helpers (sm_80+) ==========================
__device__ __forceinline__ uint32_t smem_u32(const void* p) {
    uint32_t a;
    asm("{ .reg .u64 t; cvta.to.shared.u64 t, %1; cvt.u32.u64 %0, t; }"
        : "=r"(a) : "l"(p));
    return a;
}
__device__ __forceinline__ void cp16(uint32_t dst, const void* src) {
    asm volatile("cp.async.cg.shared.global [%0], [%1], 16;" :: "r"(dst), "l"(src));
}
#define CP_COMMIT()  asm volatile("cp.async.commit_group;" ::: "memory")
#define CP_WAIT(n)   asm volatile("cp.async.wait_group %0;" :: "n"(n) : "memory")

__device__ __forceinline__ void ldsm4(uint32_t a[4], uint32_t addr) {
    asm volatile("ldmatrix.sync.aligned.m8n8.x4.shared.b16 {%0,%1,%2,%3}, [%4];"
        : "=r"(a[0]), "=r"(a[1]), "=r"(a[2]), "=r"(a[3]) : "r"(addr));
}
__device__ __forceinline__ void ldsm2(uint32_t a[2], uint32_t addr) {
    asm volatile("ldmatrix.sync.aligned.m8n8.x2.shared.b16 {%0,%1}, [%2];"
        : "=r"(a[0]), "=r"(a[1]) : "r"(addr));
}
__device__ __forceinline__ void ldsm2t(uint32_t a[2], uint32_t addr) {
    asm volatile("ldmatrix.sync.aligned.m8n8.x2.trans.shared.b16 {%0,%1}, [%2];"
        : "=r"(a[0]), "=r"(a[1]) : "r"(addr));
}
__device__ __forceinline__ void mma_fp(float d[4], const uint32_t a[4], const uint32_t b[2]) {
    asm volatile("mma.sync.aligned.m16n8k16.row.col.f32.f16.f16.f32 "
        "{%0,%1,%2,%3}, {%4,%5,%6,%7}, {%8,%9}, {%0,%1,%2,%3};"
        : "+f"(d[0]), "+f"(d[1]), "+f"(d[2]), "+f"(d[3])
        : "r"(a[0]), "r"(a[1]), "r"(a[2]), "r"(a[3]), "r"(b[0]), "r"(b[1]));
}

// fast exp on FMA pipe (no MUFU)
__device__ __forceinline__ float fexp(float x) {
    float z  = fmaxf(x, -80.f) * 1.4426950408889634f;
    float fz = z + 12582912.f;
    int   n  = __float_as_int(fz) - 0x4B400000;
    float f  = z - (float)n;
    float p  = 1.3333558146428443e-3f;
    p = fmaf(p, f, 9.6181291076284772e-3f);
    p = fmaf(p, f, 5.5504108664821580e-2f);
    p = fmaf(p, f, 2.4022650695910071e-1f);
    p = fmaf(p, f, 6.9314718055994531e-1f);
    p = fmaf(p, f, 1.0f);
    return p * __int_as_float((n + 127) << 23);
}

// ============================================================================
// fp32 -> fp16 conversions, one launch.
// ============================================================================
__global__ __launch_bounds__(256) void conv_all(
    const float* __restrict__ x,  const float* __restrict__ Wq,
    const float* __restrict__ Wk, const float* __restrict__ Wv,
    const float* __restrict__ Wo)
{
    int b = blockIdx.x;
    if (b < 2048) {
        int i = b * 256 + threadIdx.x;
        float4 v = ((const float4*)x)[i];
        __half2* hp = (__half2*)(g_xh + i * 4);
        hp[0] = __floats2half2_rn(v.x, v.y);
        hp[1] = __floats2half2_rn(v.z, v.w);
        return;
    }
    int wsel = (b - 2048) >> 10;
    int off  = (b - 2048) & 1023;
    const float* s = (wsel == 0) ? Wq : (wsel == 1) ? Wk : (wsel == 2) ? Wv : Wo;
    __half* hi = g_wh + (size_t)wsel * (E_ * E_);
    int i = off * 256 + threadIdx.x;
    float4 v = ((const float4*)s)[i];
    __half h0 = __float2half_rn(v.x), h1 = __float2half_rn(v.y);
    __half h2 = __float2half_rn(v.z), h3 = __float2half_rn(v.w);
    __half2* hp = (__half2*)(hi + i * 4);
    hp[0] = __halves2half2(h0, h1); hp[1] = __halves2half2(h2, h3);
    if (wsel == 3) {                  // only Wo keeps a lo correction
        __half l0 = __float2half_rn(v.x - __half2float(h0));
        __half l1 = __float2half_rn(v.y - __half2float(h1));
        __half l2 = __float2half_rn(v.z - __half2float(h2));
        __half l3 = __float2half_rn(v.w - __half2float(h3));
        __half2* lp = (__half2*)(g_wl + (size_t)wsel * (E_ * E_) + i * 4);
        lp[0] = __halves2half2(l0, l1); lp[1] = __halves2half2(l2, l3);
    }
}

// ============================================================================
// fp16 GEMM on mma.sync: C[128,128] = A[M,K] * B[N,K]^T  (unchanged, frozen)
// mode 0: 1 term (Wh only), x*W[z] -> q/k/v fp16 single in [H][L][64]
// mode 1: 2 terms (Wh+Wl), ao*Wo -> out fp32
// ============================================================================
#define BK    64
#define NCHK  (E_ / BK)
#define TILEB (128 * BK * 2)
#define STAGEB (3 * TILEB)
#define SMEM_MMA (2 * STAGEB)

__device__ __forceinline__ void load_tile_async(
    uint32_t dst, const __half* src, int row0, int kt, int tid)
{
#pragma unroll
    for (int it = 0; it < 4; it++) {
        int c = tid + it * 256;
        int row = c >> 3;
        int ch  = c & 7;
        const __half* sp = src + (size_t)(row0 + row) * E_ + kt + ch * 8;
        uint32_t sw = row * 128 + ((ch ^ (row & 7)) << 4);
        cp16(dst + sw, sp);
    }
}

__global__ __launch_bounds__(256) void mma_gemm(int mode, float* __restrict__ out)
{
    extern __shared__ char smem[];
    uint32_t sbase = smem_u32(smem);
    int tid  = threadIdx.x;
    int lane = tid & 31;
    int w    = tid >> 5;
    int wm   = w >> 2;
    int wn   = w & 3;
    int z    = blockIdx.z;
    int m0   = blockIdx.y * 128;
    int n0   = blockIdx.x * 128;

    const __half* A = (mode == 0) ? g_xh : g_aoh;
    int wsel = (mode == 0) ? z : 3;
    const __half* Bhi = g_wh + (size_t)wsel * (E_ * E_);
    const __half* Blo = g_wl + (size_t)wsel * (E_ * E_);
    int nt = (mode == 0) ? 1 : 2;

    float acc[4][4][4];
#pragma unroll
    for (int mi = 0; mi < 4; mi++)
#pragma unroll
        for (int ni = 0; ni < 4; ni++)
#pragma unroll
            for (int r = 0; r < 4; r++) acc[mi][ni][r] = 0.f;

    int rl = lane & 7;
    int ai = lane >> 3;
    int aci = ai >> 1;
    int arow[4];
#pragma unroll
    for (int mi = 0; mi < 4; mi++)
        arow[mi] = (wm * 64 + mi * 16 + (ai & 1) * 8 + rl) * 128;
    int bi = (lane >> 3) & 1;
    int brow[4];
#pragma unroll
    for (int ni = 0; ni < 4; ni++)
        brow[ni] = (wn * 32 + ni * 8 + rl) * 128;

    load_tile_async(sbase + 0 * TILEB, A,   m0, 0, tid);
    load_tile_async(sbase + 1 * TILEB, Bhi, n0, 0, tid);
    if (nt == 2) load_tile_async(sbase + 2 * TILEB, Blo, n0, 0, tid);
    CP_COMMIT();

    for (int kt = 0; kt < NCHK; kt++) {
        bool more = (kt + 1) < NCHK;
        if (more) {
            uint32_t nb = sbase + ((kt + 1) & 1) * STAGEB;
            int kk = (kt + 1) * BK;
            load_tile_async(nb + 0 * TILEB, A,   m0, kk, tid);
            load_tile_async(nb + 1 * TILEB, Bhi, n0, kk, tid);
            if (nt == 2) load_tile_async(nb + 2 * TILEB, Blo, n0, kk, tid);
            CP_COMMIT();
            CP_WAIT(1);
        } else {
            CP_WAIT(0);
        }
        __syncthreads();

        uint32_t st = sbase + (kt & 1) * STAGEB;
#pragma unroll
        for (int ks = 0; ks < 4; ks++) {
            uint32_t af[4][4];
            uint32_t choA = (((ks * 2 + aci) ^ rl) << 4);
            uint32_t choB = (((ks * 2 + bi) ^ rl) << 4);
#pragma unroll
            for (int mi = 0; mi < 4; mi++)
                ldsm4(af[mi], st + arow[mi] + choA);
            for (int t = 0; t < nt; t++) {
                uint32_t uB = st + TILEB + t * TILEB;
                uint32_t bf[4][2];
#pragma unroll
                for (int ni = 0; ni < 4; ni++)
                    ldsm2(bf[ni], uB + brow[ni] + choB);
#pragma unroll
                for (int mi = 0; mi < 4; mi++)
#pragma unroll
                    for (int ni = 0; ni < 4; ni++)
                        mma_fp(acc[mi][ni], af[mi], bf[ni]);
            }
        }
        __syncthreads();
    }

    int mrow = m0 + wm * 64 + (lane >> 2);
    int ncol = n0 + wn * 32 + (lane & 3) * 2;
#pragma unroll
    for (int mi = 0; mi < 4; mi++) {
#pragma unroll
        for (int ni = 0; ni < 4; ni++) {
            int n = ncol + ni * 8;
#pragma unroll
            for (int half = 0; half < 2; half++) {
                int m = mrow + mi * 16 + half * 8;
                float v0 = acc[mi][ni][half * 2], v1 = acc[mi][ni][half * 2 + 1];
                if (mode == 0) {
                    size_t o = ((size_t)(n >> 6) * L_ + m) * 64 + (n & 63);
                    __half* C = (z == 0) ? g_qh : (z == 1) ? g_kh : g_vh;
                    *(__half2*)(C + o) = __floats2half2_rn(v0, v1);
                } else {
                    *(float2*)(out + (size_t)m * E_ + n) = make_float2(v0, v1);
                }
            }
        }
    }
}

// ============================================================================
// Attention. Grid 512 = 32 q-tiles (heavy first) x 16 heads; 64-row q-tiles.
// 256 thr = 8 warps: 4 m-warps x 2 n-warps. BK=128 k-chunks.
// __launch_bounds__(256, 3): cap regs at 85 so 3 CTAs/SM are resident.
// ============================================================================
#define AT0_   0u          /* 8 KB: Q (pass1) / T cols 0..63 (pass2) */
#define AT1_   8192u       /* 8 KB: T cols 64..127 (pass2) */
#define AKV_   16384u      /* 2 bufs x 16 KB (K 128 rows in pass1, V in pass2) */
#define ABIAS_ 49152u      /* 8 KB */
#define AZP_   57344u      /* 2 x 64 floats */
#define AINVZ_ 57856u
#define ATAUT_ 58112u
#define SMEM_ATT 58368

__global__ void __launch_bounds__(256, 3) attn_kernel(
    const float* __restrict__ bias, const float* __restrict__ tau)
{
    extern __shared__ char smem[];
    uint32_t sb = smem_u32(smem);
    float* sbias = (float*)(smem + ABIAS_);
    float* szp   = (float*)(smem + AZP_);
    float* sinvz = (float*)(smem + AINVZ_);
    float* staut = (float*)(smem + ATAUT_);

    int bx  = blockIdx.x;
    int iq  = 31 - (bx >> 4);       // heavy q-tiles first
    int h   = bx & 15;
    int q0  = iq * 64;
    int nch = (q0 + 64 + 127) >> 7; // 128-row k-chunks covering [0, q0+64)

    int tid = threadIdx.x;
    int lane = tid & 31, w = tid >> 5;
    int wm = w >> 1, wn = w & 1;    // 4 m-warps x 2 n-warps
    int rl = lane & 7;
    int ai = lane >> 3, aci = ai >> 1, bi = ai & 1;
    float tauh = tau[h];
    const float scale = 0.125f;

    for (int i = tid; i < MBL_ / 4; i += 256)
        *(float4*)&sbias[i * 4] = *(const float4*)&bias[h * MBL_ + i * 4];

    const __half* qh = g_qh + (size_t)h * (L_ * 64);
    const __half* kh = g_kh + (size_t)h * (L_ * 64);
    const __half* vh = g_vh + (size_t)h * (L_ * 64);
    __half* eh = g_e + (size_t)h * L_ * L_;

    uint32_t arow = (uint32_t)((wm * 16 + (ai & 1) * 8 + rl) * 128);
    uint32_t brow8[8];
#pragma unroll
    for (int ni = 0; ni < 8; ni++)
        brow8[ni] = (uint32_t)((wn * 64 + ni * 8 + rl) * 128);

    // ---- load Q (64 rows x 128B) + K chunk 0 (128 rows x 128B) ----
#pragma unroll
    for (int it = 0; it < 2; it++) {
        int c = tid + it * 256;
        int row = c >> 3, ch = c & 7;
        uint32_t sw = row * 128 + ((ch ^ (row & 7)) << 4);
        cp16(sb + AT0_ + sw, qh + (size_t)(q0 + row) * 64 + ch * 8);
    }
#pragma unroll
    for (int it = 0; it < 4; it++) {
        int c = tid + it * 256;
        int row = c >> 3, ch = c & 7;
        uint32_t sw = row * 128 + ((ch ^ (row & 7)) << 4);
        cp16(sb + AKV_ + sw, kh + (size_t)row * 64 + ch * 8);
    }
    CP_COMMIT();

    float rs[2] = {0.f, 0.f};

    // ==================== PASS 1 ====================
    for (int j = 0; j < nch; j++) {
        int b = j & 1;
        int k0 = j * 128;
        if (j + 1 < nch) {
            uint32_t nb = sb + AKV_ + (b ^ 1) * 16384;
            int k0n = (j + 1) * 128;
#pragma unroll
            for (int it = 0; it < 4; it++) {
                int c = tid + it * 256;
                int row = c >> 3, ch = c & 7;
                uint32_t sw = row * 128 + ((ch ^ (row & 7)) << 4);
                cp16(nb + sw, kh + (size_t)(k0n + row) * 64 + ch * 8);
            }
            CP_COMMIT();
            CP_WAIT(1);
        } else {
            CP_WAIT(0);
        }
        __syncthreads();

        float sacc[8][4];
#pragma unroll
        for (int ni = 0; ni < 8; ni++)
#pragma unroll
            for (int r = 0; r < 4; r++) sacc[ni][r] = 0.f;

        uint32_t bkh = sb + AKV_ + b * 16384;
#pragma unroll
        for (int ks = 0; ks < 4; ks++) {
            uint32_t qf[4];
            uint32_t choA = (((ks * 2 + aci) ^ rl) << 4);
            uint32_t choB = (((ks * 2 + bi) ^ rl) << 4);
            ldsm4(qf, sb + AT0_ + arow + choA);
#pragma unroll
            for (int ni = 0; ni < 8; ni++) {
                uint32_t kf[2];
                ldsm2(kf, bkh + brow8[ni] + choB);
                mma_fp(sacc[ni], qf, kf);
            }
        }
        __syncthreads();    // K buf b reusable

        // epilogue: scale + bias + causal, exp, store e, Z partials
        int r = wm * 16 + (lane >> 2);
#pragma unroll
        for (int ni = 0; ni < 8; ni++) {
            int kk = k0 + wn * 64 + ni * 8 + (lane & 3) * 2;
#pragma unroll
            for (int hh = 0; hh < 2; hh++) {
                int qq = q0 + r + hh * 8;
                float s0 = sacc[ni][hh * 2]     * scale;
                float s1 = sacc[ni][hh * 2 + 1] * scale;
                int d0 = qq - kk, d1 = d0 - 1;
                float e0 = (d0 >= 0) ? fexp(s0 + sbias[d0]) : 0.f;
                float e1 = (d1 >= 0) ? fexp(s1 + sbias[d1]) : 0.f;
                *(__half2*)(eh + (size_t)qq * L_ + kk) = __floats2half2_rn(e0, e1);
                rs[hh] += e0 + e1;
            }
        }
    }

    // ---- finalize Z ----
#pragma unroll
    for (int hh = 0; hh < 2; hh++) {
        rs[hh] += __shfl_xor_sync(0xffffffffu, rs[hh], 1);
        rs[hh] += __shfl_xor_sync(0xffffffffu, rs[hh], 2);
    }
    if ((lane & 3) == 0) {
        int r0 = wm * 16 + (lane >> 2);
        szp[wn * 64 + r0]     = rs[0];
        szp[wn * 64 + r0 + 8] = rs[1];
    }
    __syncthreads();
    if (tid < 64) {
        float Zr = szp[tid] + szp[64 + tid];
        sinvz[tid] = 1.f / Zr;
        staut[tid] = tauh / (float)(q0 + tid + 1);
    }
    // prefetch V chunk 0 into buf 0
#pragma unroll
    for (int it = 0; it < 4; it++) {
        int c = tid + it * 256;
        int row = c >> 3, ch = c & 7;
        uint32_t sw = row * 128 + ((ch ^ (row & 7)) << 4);
        cp16(sb + AKV_ + sw, vh + (size_t)row * 64 + ch * 8);
    }
    CP_COMMIT();
    __syncthreads();

    // ==================== PASS 2 ====================
    float oacc[4][4];
#pragma unroll
    for (int ni = 0; ni < 4; ni++)
#pragma unroll
        for (int r = 0; r < 4; r++) oacc[ni][r] = 0.f;

    for (int j = 0; j < nch; j++) {
        int b = j & 1;
        int k0 = j * 128;
        // build T tiles (fp16, two 64-col sub-tiles) in AT0_/AT1_
#pragma unroll
        for (int it = 0; it < 4; it++) {
            int c = tid + it * 256;
            int row = c >> 4, ch = c & 15;       // 64 rows x 16 chunks of 8
            uint4 ev = *(const uint4*)(eh + (size_t)(q0 + row) * L_ + k0 + ch * 8);
            float iz = sinvz[row], tt = staut[row];
            const __half2* ep = (const __half2*)&ev;
            uint32_t tw[4];
#pragma unroll
            for (int u = 0; u < 4; u++) {
                float2 e2 = __half22float2(ep[u]);
                float t0 = fmaxf(fmaf(e2.x, iz, tt), 0.f);
                float t1 = fmaxf(fmaf(e2.y, iz, tt), 0.f);
                __half2 tp = __floats2half2_rn(t0, t1);
                tw[u] = *(uint32_t*)&tp;
            }
            int sub = ch >> 3;                   // 0: cols 0..63, 1: 64..127
            int lch = ch & 7;
            uint32_t sw = row * 128 + ((lch ^ (row & 7)) << 4);
            *(uint4*)(smem + (sub ? AT1_ : AT0_) + sw) = make_uint4(tw[0], tw[1], tw[2], tw[3]);
        }
        if (j + 1 < nch) {
            uint32_t nb = sb + AKV_ + (b ^ 1) * 16384;
            int k0n = (j + 1) * 128;
#pragma unroll
            for (int it = 0; it < 4; it++) {
                int c = tid + it * 256;
                int row = c >> 3, ch = c & 7;
                uint32_t sw = row * 128 + ((ch ^ (row & 7)) << 4);
                cp16(nb + sw, vh + (size_t)(k0n + row) * 64 + ch * 8);
            }
            CP_COMMIT();
            CP_WAIT(1);
        } else {
            CP_WAIT(0);
        }
        __syncthreads();

        uint32_t bv = sb + AKV_ + b * 16384;
        int krl = lane & 15;
#pragma unroll
        for (int ks = 0; ks < 8; ks++) {
            int lks = ks & 3;
            uint32_t tbase = (ks < 4) ? AT0_ : AT1_;
            uint32_t tf[4], vf[4][2];
            uint32_t choA = (((lks * 2 + aci) ^ rl) << 4);
            ldsm4(tf, sb + tbase + arow + choA);
            int kr = ks * 16 + krl;              // 0..127 V rows
#pragma unroll
            for (int ni = 0; ni < 4; ni++) {
                uint32_t off = kr * 128 + (((wn * 4 + ni) ^ (kr & 7)) << 4);
                ldsm2t(vf[ni], bv + off);
            }
#pragma unroll
            for (int ni = 0; ni < 4; ni++)
                mma_fp(oacc[ni], tf, vf[ni]);
        }
        __syncthreads();    // T + V buf free for next chunk
    }

    // ---- O -> g_aoh fp16 ----
#pragma unroll
    for (int ni = 0; ni < 4; ni++) {
        int c = wn * 32 + ni * 8 + (lane & 3) * 2;
#pragma unroll
        for (int hh = 0; hh < 2; hh++) {
            int q = q0 + wm * 16 + (lane >> 2) + hh * 8;
            float v0 = oacc[ni][hh * 2], v1 = oacc[ni][hh * 2 + 1];
            size_t o = (size_t)q * E_ + h * 64 + c;
            *(__half2*)(g_aoh + o) = __floats2half2_rn(v0, v1);
        }
    }
}

// ============================================================================
extern "C" void kernel_launch(void* const* d_in, const int* in_sizes, int n_in,
                              void* d_out, int out_size)
{
    (void)in_sizes; (void)n_in; (void)out_size;
    const float* x    = (const float*)d_in[0];
    const float* Wq   = (const float*)d_in[1];
    const float* Wk   = (const float*)d_in[2];
    const float* Wv   = (const float*)d_in[3];
    const float* Wo   = (const float*)d_in[4];
    const float* bias = (const float*)d_in[5];
    const float* tau  = (const float*)d_in[6];
    float* out = (float*)d_out;

    cudaFuncSetAttribute(mma_gemm, cudaFuncAttributeMaxDynamicSharedMemorySize, SMEM_MMA);
    cudaFuncSetAttribute(attn_kernel, cudaFuncAttributeMaxDynamicSharedMemorySize, SMEM_ATT);

    conv_all<<<2048 + 4 * 1024, 256>>>(x, Wq, Wk, Wv, Wo);
    mma_gemm<<<dim3(E_ / 128, L_ / 128, 3), 256, SMEM_MMA>>>(0, nullptr);
    attn_kernel<<<512, 256, SMEM_ATT>>>(bias, tau);
    mma_gemm<<<dim3(E_ / 128, L_ / 128, 1), 256, SMEM_MMA>>>(1, out);
}

// round 15
// speedup vs baseline: 1.4557x; 1.0118x over previous
#include <cuda_runtime.h>
#include <cuda_bf16.h>
#include <cuda_fp16.h>
#include <cstdint>
#include <math.h>

#define L_   2048
#define E_   1024
#define H_   16
#define D_   64
#define MBL_ 2048

// ---------------- device scratch (static; allocation-free) -----------------
__device__ __half g_e[(size_t)H_ * L_ * L_];    // exp(s), unnormalized, fp16

// fp16 operands for the big GEMMs
__device__ __half g_xh[L_ * E_];
__device__ __half g_wh[4 * E_ * E_], g_wl[4 * E_ * E_];   // lo used for Wo only
__device__ __half g_aoh[L_ * E_];
// fp16 attention operands, [H][L][64] (all single-rounded)
__device__ __half g_qh[H_ * L_ * D_];
__device__ __half g_kh[H_ * L_ * D_];
__device__ __half g_vh[H_ * L_ * D_];

// ============================ PTX helpers (sm_80+) ==========================
__device__ __forceinline__ uint32_t smem_u32(const void* p) {
    uint32_t a;
    asm("{ .reg .u64 t; cvta.to.shared.u64 t, %1; cvt.u32.u64 %0, t; }"
        : "=r"(a) : "l"(p));
    return a;
}
__device__ __forceinline__ void cp16(uint32_t dst, const void* src) {
    asm volatile("cp.async.cg.shared.global [%0], [%1], 16;" :: "r"(dst), "l"(src));
}
#define CP_COMMIT()  asm volatile("cp.async.commit_group;" ::: "memory")
#define CP_WAIT(n)   asm volatile("cp.async.wait_group %0;" :: "n"(n) : "memory")

__device__ __forceinline__ void ldsm4(uint32_t a[4], uint32_t addr) {
    asm volatile("ldmatrix.sync.aligned.m8n8.x4.shared.b16 {%0,%1,%2,%3}, [%4];"
        : "=r"(a[0]), "=r"(a[1]), "=r"(a[2]), "=r"(a[3]) : "r"(addr));
}
__device__ __forceinline__ void ldsm2(uint32_t a[2], uint32_t addr) {
    asm volatile("ldmatrix.sync.aligned.m8n8.x2.shared.b16 {%0,%1}, [%2];"
        : "=r"(a[0]), "=r"(a[1]) : "r"(addr));
}
__device__ __forceinline__ void ldsm2t(uint32_t a[2], uint32_t addr) {
    asm volatile("ldmatrix.sync.aligned.m8n8.x2.trans.shared.b16 {%0,%1}, [%2];"
        : "=r"(a[0]), "=r"(a[1]) : "r"(addr));
}
__device__ __forceinline__ void mma_fp(float d[4], const uint32_t a[4], const uint32_t b[2]) {
    asm volatile("mma.sync.aligned.m16n8k16.row.col.f32.f16.f16.f32 "
        "{%0,%1,%2,%3}, {%4,%5,%6,%7}, {%8,%9}, {%0,%1,%2,%3};"
        : "+f"(d[0]), "+f"(d[1]), "+f"(d[2]), "+f"(d[3])
        : "r"(a[0]), "r"(a[1]), "r"(a[2]), "r"(a[3]), "r"(b[0]), "r"(b[1]));
}

// fast exp on FMA pipe (no MUFU)
__device__ __forceinline__ float fexp(float x) {
    float z  = fmaxf(x, -80.f) * 1.4426950408889634f;
    float fz = z + 12582912.f;
    int   n  = __float_as_int(fz) - 0x4B400000;
    float f  = z - (float)n;
    float p  = 1.3333558146428443e-3f;
    p = fmaf(p, f, 9.6181291076284772e-3f);
    p = fmaf(p, f, 5.5504108664821580e-2f);
    p = fmaf(p, f, 2.4022650695910071e-1f);
    p = fmaf(p, f, 6.9314718055994531e-1f);
    p = fmaf(p, f, 1.0f);
    return p * __int_as_float((n + 127) << 23);
}

// ============================================================================
// fp32 -> fp16 conversions, one launch.
// ============================================================================
__global__ __launch_bounds__(256) void conv_all(
    const float* __restrict__ x,  const float* __restrict__ Wq,
    const float* __restrict__ Wk, const float* __restrict__ Wv,
    const float* __restrict__ Wo)
{
    int b = blockIdx.x;
    if (b < 2048) {
        int i = b * 256 + threadIdx.x;
        float4 v = ((const float4*)x)[i];
        __half2* hp = (__half2*)(g_xh + i * 4);
        hp[0] = __floats2half2_rn(v.x, v.y);
        hp[1] = __floats2half2_rn(v.z, v.w);
        return;
    }
    int wsel = (b - 2048) >> 10;
    int off  = (b - 2048) & 1023;
    const float* s = (wsel == 0) ? Wq : (wsel == 1) ? Wk : (wsel == 2) ? Wv : Wo;
    __half* hi = g_wh + (size_t)wsel * (E_ * E_);
    int i = off * 256 + threadIdx.x;
    float4 v = ((const float4*)s)[i];
    __half h0 = __float2half_rn(v.x), h1 = __float2half_rn(v.y);
    __half h2 = __float2half_rn(v.z), h3 = __float2half_rn(v.w);
    __half2* hp = (__half2*)(hi + i * 4);
    hp[0] = __halves2half2(h0, h1); hp[1] = __halves2half2(h2, h3);
    if (wsel == 3) {                  // only Wo keeps a lo correction
        __half l0 = __float2half_rn(v.x - __half2float(h0));
        __half l1 = __float2half_rn(v.y - __half2float(h1));
        __half l2 = __float2half_rn(v.z - __half2float(h2));
        __half l3 = __float2half_rn(v.w - __half2float(h3));
        __half2* lp = (__half2*)(g_wl + (size_t)wsel * (E_ * E_) + i * 4);
        lp[0] = __halves2half2(l0, l1); lp[1] = __halves2half2(l2, l3);
    }
}

// ============================================================================
// fp16 GEMM on mma.sync: C[128,128] = A[M,K] * B[N,K]^T
// mode 0: 1 term (Wh only), 64 KB smem (2 x 32 KB stages), 2 CTAs/SM
// mode 1: 2 terms (Wh+Wl), 96 KB smem (2 x 48 KB stages)
// ============================================================================
#define BK    64
#define NCHK  (E_ / BK)
#define TILEB (128 * BK * 2)        // 16 KB per 128xBK fp16 tile
#define SMEM_MMA1 (2 * 2 * TILEB)   // mode 0: 64 KB
#define SMEM_MMA2 (2 * 3 * TILEB)   // mode 1: 96 KB

__device__ __forceinline__ void load_tile_async(
    uint32_t dst, const __half* src, int row0, int kt, int tid)
{
#pragma unroll
    for (int it = 0; it < 4; it++) {
        int c = tid + it * 256;
        int row = c >> 3;
        int ch  = c & 7;
        const __half* sp = src + (size_t)(row0 + row) * E_ + kt + ch * 8;
        uint32_t sw = row * 128 + ((ch ^ (row & 7)) << 4);
        cp16(dst + sw, sp);
    }
}

__global__ void __launch_bounds__(256, 2) mma_gemm(int mode, float* __restrict__ out)
{
    extern __shared__ char smem[];
    uint32_t sbase = smem_u32(smem);
    int tid  = threadIdx.x;
    int lane = tid & 31;
    int w    = tid >> 5;
    int wm   = w >> 2;
    int wn   = w & 3;
    int z    = blockIdx.z;
    int m0   = blockIdx.y * 128;
    int n0   = blockIdx.x * 128;

    const __half* A = (mode == 0) ? g_xh : g_aoh;
    int wsel = (mode == 0) ? z : 3;
    const __half* Bhi = g_wh + (size_t)wsel * (E_ * E_);
    const __half* Blo = g_wl + (size_t)wsel * (E_ * E_);
    int nt = (mode == 0) ? 1 : 2;
    uint32_t stageb = (nt == 1) ? (2 * TILEB) : (3 * TILEB);

    float acc[4][4][4];
#pragma unroll
    for (int mi = 0; mi < 4; mi++)
#pragma unroll
        for (int ni = 0; ni < 4; ni++)
#pragma unroll
            for (int r = 0; r < 4; r++) acc[mi][ni][r] = 0.f;

    int rl = lane & 7;
    int ai = lane >> 3;
    int aci = ai >> 1;
    int arow[4];
#pragma unroll
    for (int mi = 0; mi < 4; mi++)
        arow[mi] = (wm * 64 + mi * 16 + (ai & 1) * 8 + rl) * 128;
    int bi = (lane >> 3) & 1;
    int brow[4];
#pragma unroll
    for (int ni = 0; ni < 4; ni++)
        brow[ni] = (wn * 32 + ni * 8 + rl) * 128;

    load_tile_async(sbase + 0 * TILEB, A,   m0, 0, tid);
    load_tile_async(sbase + 1 * TILEB, Bhi, n0, 0, tid);
    if (nt == 2) load_tile_async(sbase + 2 * TILEB, Blo, n0, 0, tid);
    CP_COMMIT();

    for (int kt = 0; kt < NCHK; kt++) {
        bool more = (kt + 1) < NCHK;
        if (more) {
            uint32_t nb = sbase + ((kt + 1) & 1) * stageb;
            int kk = (kt + 1) * BK;
            load_tile_async(nb + 0 * TILEB, A,   m0, kk, tid);
            load_tile_async(nb + 1 * TILEB, Bhi, n0, kk, tid);
            if (nt == 2) load_tile_async(nb + 2 * TILEB, Blo, n0, kk, tid);
            CP_COMMIT();
            CP_WAIT(1);
        } else {
            CP_WAIT(0);
        }
        __syncthreads();

        uint32_t st = sbase + (kt & 1) * stageb;
#pragma unroll
        for (int ks = 0; ks < 4; ks++) {
            uint32_t af[4][4];
            uint32_t choA = (((ks * 2 + aci) ^ rl) << 4);
            uint32_t choB = (((ks * 2 + bi) ^ rl) << 4);
#pragma unroll
            for (int mi = 0; mi < 4; mi++)
                ldsm4(af[mi], st + arow[mi] + choA);
            for (int t = 0; t < nt; t++) {
                uint32_t uB = st + TILEB + t * TILEB;
                uint32_t bf[4][2];
#pragma unroll
                for (int ni = 0; ni < 4; ni++)
                    ldsm2(bf[ni], uB + brow[ni] + choB);
#pragma unroll
                for (int mi = 0; mi < 4; mi++)
#pragma unroll
                    for (int ni = 0; ni < 4; ni++)
                        mma_fp(acc[mi][ni], af[mi], bf[ni]);
            }
        }
        __syncthreads();
    }

    int mrow = m0 + wm * 64 + (lane >> 2);
    int ncol = n0 + wn * 32 + (lane & 3) * 2;
#pragma unroll
    for (int mi = 0; mi < 4; mi++) {
#pragma unroll
        for (int ni = 0; ni < 4; ni++) {
            int n = ncol + ni * 8;
#pragma unroll
            for (int half = 0; half < 2; half++) {
                int m = mrow + mi * 16 + half * 8;
                float v0 = acc[mi][ni][half * 2], v1 = acc[mi][ni][half * 2 + 1];
                if (mode == 0) {
                    size_t o = ((size_t)(n >> 6) * L_ + m) * 64 + (n & 63);
                    __half* C = (z == 0) ? g_qh : (z == 1) ? g_kh : g_vh;
                    *(__half2*)(C + o) = __floats2half2_rn(v0, v1);
                } else {
                    *(float2*)(out + (size_t)m * E_ + n) = make_float2(v0, v1);
                }
            }
        }
    }
}

// ============================================================================
// Attention (frozen from round 14). Grid 512, 64-row q-tiles, BK=128 chunks,
// __launch_bounds__(256, 3) for 3 CTAs/SM.
// ============================================================================
#define AT0_   0u          /* 8 KB: Q (pass1) / T cols 0..63 (pass2) */
#define AT1_   8192u       /* 8 KB: T cols 64..127 (pass2) */
#define AKV_   16384u      /* 2 bufs x 16 KB (K 128 rows in pass1, V in pass2) */
#define ABIAS_ 49152u      /* 8 KB */
#define AZP_   57344u      /* 2 x 64 floats */
#define AINVZ_ 57856u
#define ATAUT_ 58112u
#define SMEM_ATT 58368

__global__ void __launch_bounds__(256, 3) attn_kernel(
    const float* __restrict__ bias, const float* __restrict__ tau)
{
    extern __shared__ char smem[];
    uint32_t sb = smem_u32(smem);
    float* sbias = (float*)(smem + ABIAS_);
    float* szp   = (float*)(smem + AZP_);
    float* sinvz = (float*)(smem + AINVZ_);
    float* staut = (float*)(smem + ATAUT_);

    int bx  = blockIdx.x;
    int iq  = 31 - (bx >> 4);       // heavy q-tiles first
    int h   = bx & 15;
    int q0  = iq * 64;
    int nch = (q0 + 64 + 127) >> 7; // 128-row k-chunks covering [0, q0+64)

    int tid = threadIdx.x;
    int lane = tid & 31, w = tid >> 5;
    int wm = w >> 1, wn = w & 1;    // 4 m-warps x 2 n-warps
    int rl = lane & 7;
    int ai = lane >> 3, aci = ai >> 1, bi = ai & 1;
    float tauh = tau[h];
    const float scale = 0.125f;

    for (int i = tid; i < MBL_ / 4; i += 256)
        *(float4*)&sbias[i * 4] = *(const float4*)&bias[h * MBL_ + i * 4];

    const __half* qh = g_qh + (size_t)h * (L_ * 64);
    const __half* kh = g_kh + (size_t)h * (L_ * 64);
    const __half* vh = g_vh + (size_t)h * (L_ * 64);
    __half* eh = g_e + (size_t)h * L_ * L_;

    uint32_t arow = (uint32_t)((wm * 16 + (ai & 1) * 8 + rl) * 128);
    uint32_t brow8[8];
#pragma unroll
    for (int ni = 0; ni < 8; ni++)
        brow8[ni] = (uint32_t)((wn * 64 + ni * 8 + rl) * 128);

    // ---- load Q (64 rows x 128B) + K chunk 0 (128 rows x 128B) ----
#pragma unroll
    for (int it = 0; it < 2; it++) {
        int c = tid + it * 256;
        int row = c >> 3, ch = c & 7;
        uint32_t sw = row * 128 + ((ch ^ (row & 7)) << 4);
        cp16(sb + AT0_ + sw, qh + (size_t)(q0 + row) * 64 + ch * 8);
    }
#pragma unroll
    for (int it = 0; it < 4; it++) {
        int c = tid + it * 256;
        int row = c >> 3, ch = c & 7;
        uint32_t sw = row * 128 + ((ch ^ (row & 7)) << 4);
        cp16(sb + AKV_ + sw, kh + (size_t)row * 64 + ch * 8);
    }
    CP_COMMIT();

    float rs[2] = {0.f, 0.f};

    // ==================== PASS 1 ====================
    for (int j = 0; j < nch; j++) {
        int b = j & 1;
        int k0 = j * 128;
        if (j + 1 < nch) {
            uint32_t nb = sb + AKV_ + (b ^ 1) * 16384;
            int k0n = (j + 1) * 128;
#pragma unroll
            for (int it = 0; it < 4; it++) {
                int c = tid + it * 256;
                int row = c >> 3, ch = c & 7;
                uint32_t sw = row * 128 + ((ch ^ (row & 7)) << 4);
                cp16(nb + sw, kh + (size_t)(k0n + row) * 64 + ch * 8);
            }
            CP_COMMIT();
            CP_WAIT(1);
        } else {
            CP_WAIT(0);
        }
        __syncthreads();

        float sacc[8][4];
#pragma unroll
        for (int ni = 0; ni < 8; ni++)
#pragma unroll
            for (int r = 0; r < 4; r++) sacc[ni][r] = 0.f;

        uint32_t bkh = sb + AKV_ + b * 16384;
#pragma unroll
        for (int ks = 0; ks < 4; ks++) {
            uint32_t qf[4];
            uint32_t choA = (((ks * 2 + aci) ^ rl) << 4);
            uint32_t choB = (((ks * 2 + bi) ^ rl) << 4);
            ldsm4(qf, sb + AT0_ + arow + choA);
#pragma unroll
            for (int ni = 0; ni < 8; ni++) {
                uint32_t kf[2];
                ldsm2(kf, bkh + brow8[ni] + choB);
                mma_fp(sacc[ni], qf, kf);
            }
        }
        __syncthreads();    // K buf b reusable

        // epilogue: scale + bias + causal, exp, store e, Z partials
        int r = wm * 16 + (lane >> 2);
#pragma unroll
        for (int ni = 0; ni < 8; ni++) {
            int kk = k0 + wn * 64 + ni * 8 + (lane & 3) * 2;
#pragma unroll
            for (int hh = 0; hh < 2; hh++) {
                int qq = q0 + r + hh * 8;
                float s0 = sacc[ni][hh * 2]     * scale;
                float s1 = sacc[ni][hh * 2 + 1] * scale;
                int d0 = qq - kk, d1 = d0 - 1;
                float e0 = (d0 >= 0) ? fexp(s0 + sbias[d0]) : 0.f;
                float e1 = (d1 >= 0) ? fexp(s1 + sbias[d1]) : 0.f;
                *(__half2*)(eh + (size_t)qq * L_ + kk) = __floats2half2_rn(e0, e1);
                rs[hh] += e0 + e1;
            }
        }
    }

    // ---- finalize Z ----
#pragma unroll
    for (int hh = 0; hh < 2; hh++) {
        rs[hh] += __shfl_xor_sync(0xffffffffu, rs[hh], 1);
        rs[hh] += __shfl_xor_sync(0xffffffffu, rs[hh], 2);
    }
    if ((lane & 3) == 0) {
        int r0 = wm * 16 + (lane >> 2);
        szp[wn * 64 + r0]     = rs[0];
        szp[wn * 64 + r0 + 8] = rs[1];
    }
    __syncthreads();
    if (tid < 64) {
        float Zr = szp[tid] + szp[64 + tid];
        sinvz[tid] = 1.f / Zr;
        staut[tid] = tauh / (float)(q0 + tid + 1);
    }
    // prefetch V chunk 0 into buf 0
#pragma unroll
    for (int it = 0; it < 4; it++) {
        int c = tid + it * 256;
        int row = c >> 3, ch = c & 7;
        uint32_t sw = row * 128 + ((ch ^ (row & 7)) << 4);
        cp16(sb + AKV_ + sw, vh + (size_t)row * 64 + ch * 8);
    }
    CP_COMMIT();
    __syncthreads();

    // ==================== PASS 2 ====================
    float oacc[4][4];
#pragma unroll
    for (int ni = 0; ni < 4; ni++)
#pragma unroll
        for (int r = 0; r < 4; r++) oacc[ni][r] = 0.f;

    for (int j = 0; j < nch; j++) {
        int b = j & 1;
        int k0 = j * 128;
        // build T tiles (fp16, two 64-col sub-tiles) in AT0_/AT1_
#pragma unroll
        for (int it = 0; it < 4; it++) {
            int c = tid + it * 256;
            int row = c >> 4, ch = c & 15;       // 64 rows x 16 chunks of 8
            uint4 ev = *(const uint4*)(eh + (size_t)(q0 + row) * L_ + k0 + ch * 8);
            float iz = sinvz[row], tt = staut[row];
            const __half2* ep = (const __half2*)&ev;
            uint32_t tw[4];
#pragma unroll
            for (int u = 0; u < 4; u++) {
                float2 e2 = __half22float2(ep[u]);
                float t0 = fmaxf(fmaf(e2.x, iz, tt), 0.f);
                float t1 = fmaxf(fmaf(e2.y, iz, tt), 0.f);
                __half2 tp = __floats2half2_rn(t0, t1);
                tw[u] = *(uint32_t*)&tp;
            }
            int sub = ch >> 3;                   // 0: cols 0..63, 1: 64..127
            int lch = ch & 7;
            uint32_t sw = row * 128 + ((lch ^ (row & 7)) << 4);
            *(uint4*)(smem + (sub ? AT1_ : AT0_) + sw) = make_uint4(tw[0], tw[1], tw[2], tw[3]);
        }
        if (j + 1 < nch) {
            uint32_t nb = sb + AKV_ + (b ^ 1) * 16384;
            int k0n = (j + 1) * 128;
#pragma unroll
            for (int it = 0; it < 4; it++) {
                int c = tid + it * 256;
                int row = c >> 3, ch = c & 7;
                uint32_t sw = row * 128 + ((ch ^ (row & 7)) << 4);
                cp16(nb + sw, vh + (size_t)(k0n + row) * 64 + ch * 8);
            }
            CP_COMMIT();
            CP_WAIT(1);
        } else {
            CP_WAIT(0);
        }
        __syncthreads();

        uint32_t bv = sb + AKV_ + b * 16384;
        int krl = lane & 15;
#pragma unroll
        for (int ks = 0; ks < 8; ks++) {
            int lks = ks & 3;
            uint32_t tbase = (ks < 4) ? AT0_ : AT1_;
            uint32_t tf[4], vf[4][2];
            uint32_t choA = (((lks * 2 + aci) ^ rl) << 4);
            ldsm4(tf, sb + tbase + arow + choA);
            int kr = ks * 16 + krl;              // 0..127 V rows
#pragma unroll
            for (int ni = 0; ni < 4; ni++) {
                uint32_t off = kr * 128 + (((wn * 4 + ni) ^ (kr & 7)) << 4);
                ldsm2t(vf[ni], bv + off);
            }
#pragma unroll
            for (int ni = 0; ni < 4; ni++)
                mma_fp(oacc[ni], tf, vf[ni]);
        }
        __syncthreads();    // T + V buf free for next chunk
    }

    // ---- O -> g_aoh fp16 ----
#pragma unroll
    for (int ni = 0; ni < 4; ni++) {
        int c = wn * 32 + ni * 8 + (lane & 3) * 2;
#pragma unroll
        for (int hh = 0; hh < 2; hh++) {
            int q = q0 + wm * 16 + (lane >> 2) + hh * 8;
            float v0 = oacc[ni][hh * 2], v1 = oacc[ni][hh * 2 + 1];
            size_t o = (size_t)q * E_ + h * 64 + c;
            *(__half2*)(g_aoh + o) = __floats2half2_rn(v0, v1);
        }
    }
}

// ============================================================================
extern "C" void kernel_launch(void* const* d_in, const int* in_sizes, int n_in,
                              void* d_out, int out_size)
{
    (void)in_sizes; (void)n_in; (void)out_size;
    const float* x    = (const float*)d_in[0];
    const float* Wq   = (const float*)d_in[1];
    const float* Wk   = (const float*)d_in[2];
    const float* Wv   = (const float*)d_in[3];
    const float* Wo   = (const float*)d_in[4];
    const float* bias = (const float*)d_in[5];
    const float* tau  = (const float*)d_in[6];
    float* out = (float*)d_out;

    cudaFuncSetAttribute(mma_gemm, cudaFuncAttributeMaxDynamicSharedMemorySize, SMEM_MMA2);
    cudaFuncSetAttribute(attn_kernel, cudaFuncAttributeMaxDynamicSharedMemorySize, SMEM_ATT);

    conv_all<<<2048 + 4 * 1024, 256>>>(x, Wq, Wk, Wv, Wo);
    mma_gemm<<<dim3(E_ / 128, L_ / 128, 3), 256, SMEM_MMA1>>>(0, nullptr);
    attn_kernel<<<512, 256, SMEM_ATT>>>(bias, tau);
    mma_gemm<<<dim3(E_ / 128, L_ / 128, 1), 256, SMEM_MMA2>>>(1, out);
}

// round 16
// speedup vs baseline: 1.5369x; 1.0558x over previous
#include <cuda_runtime.h>
#include <cuda_bf16.h>
#include <cuda_fp16.h>
#include <cstdint>
#include <math.h>

#define L_   2048
#define E_   1024
#define H_   16
#define D_   64
#define MBL_ 2048

// ---------------- device scratch (static; allocation-free) -----------------
// e in PV-fragment layout: [h][iq(32)][chunk(16)][slot(32)][wm(4)*32+lane] u32
__device__ uint32_t g_ef[(size_t)H_ * 32 * 16 * 4096];

// fp16 operands for the big GEMMs
__device__ __half g_xh[L_ * E_];
__device__ __half g_wh[4 * E_ * E_], g_wl[4 * E_ * E_];   // lo used for Wo only
__device__ __half g_aoh[L_ * E_];
// fp16 attention operands, [H][L][64] (all single-rounded)
__device__ __half g_qh[H_ * L_ * D_];
__device__ __half g_kh[H_ * L_ * D_];
__device__ __half g_vh[H_ * L_ * D_];

// ============================ PTX helpers (sm_80+) ==========================
__device__ __forceinline__ uint32_t smem_u32(const void* p) {
    uint32_t a;
    asm("{ .reg .u64 t; cvta.to.shared.u64 t, %1; cvt.u32.u64 %0, t; }"
        : "=r"(a) : "l"(p));
    return a;
}
__device__ __forceinline__ void cp16(uint32_t dst, const void* src) {
    asm volatile("cp.async.cg.shared.global [%0], [%1], 16;" :: "r"(dst), "l"(src));
}
#define CP_COMMIT()  asm volatile("cp.async.commit_group;" ::: "memory")
#define CP_WAIT(n)   asm volatile("cp.async.wait_group %0;" :: "n"(n) : "memory")

__device__ __forceinline__ void ldsm4(uint32_t a[4], uint32_t addr) {
    asm volatile("ldmatrix.sync.aligned.m8n8.x4.shared.b16 {%0,%1,%2,%3}, [%4];"
        : "=r"(a[0]), "=r"(a[1]), "=r"(a[2]), "=r"(a[3]) : "r"(addr));
}
__device__ __forceinline__ void ldsm2(uint32_t a[2], uint32_t addr) {
    asm volatile("ldmatrix.sync.aligned.m8n8.x2.shared.b16 {%0,%1}, [%2];"
        : "=r"(a[0]), "=r"(a[1]) : "r"(addr));
}
__device__ __forceinline__ void ldsm2t(uint32_t a[2], uint32_t addr) {
    asm volatile("ldmatrix.sync.aligned.m8n8.x2.trans.shared.b16 {%0,%1}, [%2];"
        : "=r"(a[0]), "=r"(a[1]) : "r"(addr));
}
__device__ __forceinline__ void mma_fp(float d[4], const uint32_t a[4], const uint32_t b[2]) {
    asm volatile("mma.sync.aligned.m16n8k16.row.col.f32.f16.f16.f32 "
        "{%0,%1,%2,%3}, {%4,%5,%6,%7}, {%8,%9}, {%0,%1,%2,%3};"
        : "+f"(d[0]), "+f"(d[1]), "+f"(d[2]), "+f"(d[3])
        : "r"(a[0]), "r"(a[1]), "r"(a[2]), "r"(a[3]), "r"(b[0]), "r"(b[1]));
}

// fast exp on FMA pipe (no MUFU)
__device__ __forceinline__ float fexp(float x) {
    float z  = fmaxf(x, -80.f) * 1.4426950408889634f;
    float fz = z + 12582912.f;
    int   n  = __float_as_int(fz) - 0x4B400000;
    float f  = z - (float)n;
    float p  = 1.3333558146428443e-3f;
    p = fmaf(p, f, 9.6181291076284772e-3f);
    p = fmaf(p, f, 5.5504108664821580e-2f);
    p = fmaf(p, f, 2.4022650695910071e-1f);
    p = fmaf(p, f, 6.9314718055994531e-1f);
    p = fmaf(p, f, 1.0f);
    return p * __int_as_float((n + 127) << 23);
}

// relu(e * iz + tt) on a packed half2, returned packed
__device__ __forceinline__ uint32_t trelu2(uint32_t e, float iz, float tt) {
    float2 f = __half22float2(*(__half2*)&e);
    float t0 = fmaxf(fmaf(f.x, iz, tt), 0.f);
    float t1 = fmaxf(fmaf(f.y, iz, tt), 0.f);
    __half2 r = __floats2half2_rn(t0, t1);
    return *(uint32_t*)&r;
}

// ============================================================================
// fp32 -> fp16 conversions, one launch.
// ============================================================================
__global__ __launch_bounds__(256) void conv_all(
    const float* __restrict__ x,  const float* __restrict__ Wq,
    const float* __restrict__ Wk, const float* __restrict__ Wv,
    const float* __restrict__ Wo)
{
    int b = blockIdx.x;
    if (b < 2048) {
        int i = b * 256 + threadIdx.x;
        float4 v = ((const float4*)x)[i];
        __half2* hp = (__half2*)(g_xh + i * 4);
        hp[0] = __floats2half2_rn(v.x, v.y);
        hp[1] = __floats2half2_rn(v.z, v.w);
        return;
    }
    int wsel = (b - 2048) >> 10;
    int off  = (b - 2048) & 1023;
    const float* s = (wsel == 0) ? Wq : (wsel == 1) ? Wk : (wsel == 2) ? Wv : Wo;
    __half* hi = g_wh + (size_t)wsel * (E_ * E_);
    int i = off * 256 + threadIdx.x;
    float4 v = ((const float4*)s)[i];
    __half h0 = __float2half_rn(v.x), h1 = __float2half_rn(v.y);
    __half h2 = __float2half_rn(v.z), h3 = __float2half_rn(v.w);
    __half2* hp = (__half2*)(hi + i * 4);
    hp[0] = __halves2half2(h0, h1); hp[1] = __halves2half2(h2, h3);
    if (wsel == 3) {                  // only Wo keeps a lo correction
        __half l0 = __float2half_rn(v.x - __half2float(h0));
        __half l1 = __float2half_rn(v.y - __half2float(h1));
        __half l2 = __float2half_rn(v.z - __half2float(h2));
        __half l3 = __float2half_rn(v.w - __half2float(h3));
        __half2* lp = (__half2*)(g_wl + (size_t)wsel * (E_ * E_) + i * 4);
        lp[0] = __halves2half2(l0, l1); lp[1] = __halves2half2(l2, l3);
    }
}

// ============================================================================
// fp16 GEMM on mma.sync: C[128,128] = A[M,K] * B[N,K]^T  (frozen)
// ============================================================================
#define BK    64
#define NCHK  (E_ / BK)
#define TILEB (128 * BK * 2)
#define SMEM_MMA1 (2 * 2 * TILEB)
#define SMEM_MMA2 (2 * 3 * TILEB)

__device__ __forceinline__ void load_tile_async(
    uint32_t dst, const __half* src, int row0, int kt, int tid)
{
#pragma unroll
    for (int it = 0; it < 4; it++) {
        int c = tid + it * 256;
        int row = c >> 3;
        int ch  = c & 7;
        const __half* sp = src + (size_t)(row0 + row) * E_ + kt + ch * 8;
        uint32_t sw = row * 128 + ((ch ^ (row & 7)) << 4);
        cp16(dst + sw, sp);
    }
}

__global__ void __launch_bounds__(256, 2) mma_gemm(int mode, float* __restrict__ out)
{
    extern __shared__ char smem[];
    uint32_t sbase = smem_u32(smem);
    int tid  = threadIdx.x;
    int lane = tid & 31;
    int w    = tid >> 5;
    int wm   = w >> 2;
    int wn   = w & 3;
    int z    = blockIdx.z;
    int m0   = blockIdx.y * 128;
    int n0   = blockIdx.x * 128;

    const __half* A = (mode == 0) ? g_xh : g_aoh;
    int wsel = (mode == 0) ? z : 3;
    const __half* Bhi = g_wh + (size_t)wsel * (E_ * E_);
    const __half* Blo = g_wl + (size_t)wsel * (E_ * E_);
    int nt = (mode == 0) ? 1 : 2;
    uint32_t stageb = (nt == 1) ? (2 * TILEB) : (3 * TILEB);

    float acc[4][4][4];
#pragma unroll
    for (int mi = 0; mi < 4; mi++)
#pragma unroll
        for (int ni = 0; ni < 4; ni++)
#pragma unroll
            for (int r = 0; r < 4; r++) acc[mi][ni][r] = 0.f;

    int rl = lane & 7;
    int ai = lane >> 3;
    int aci = ai >> 1;
    int arow[4];
#pragma unroll
    for (int mi = 0; mi < 4; mi++)
        arow[mi] = (wm * 64 + mi * 16 + (ai & 1) * 8 + rl) * 128;
    int bi = (lane >> 3) & 1;
    int brow[4];
#pragma unroll
    for (int ni = 0; ni < 4; ni++)
        brow[ni] = (wn * 32 + ni * 8 + rl) * 128;

    load_tile_async(sbase + 0 * TILEB, A,   m0, 0, tid);
    load_tile_async(sbase + 1 * TILEB, Bhi, n0, 0, tid);
    if (nt == 2) load_tile_async(sbase + 2 * TILEB, Blo, n0, 0, tid);
    CP_COMMIT();

    for (int kt = 0; kt < NCHK; kt++) {
        bool more = (kt + 1) < NCHK;
        if (more) {
            uint32_t nb = sbase + ((kt + 1) & 1) * stageb;
            int kk = (kt + 1) * BK;
            load_tile_async(nb + 0 * TILEB, A,   m0, kk, tid);
            load_tile_async(nb + 1 * TILEB, Bhi, n0, kk, tid);
            if (nt == 2) load_tile_async(nb + 2 * TILEB, Blo, n0, kk, tid);
            CP_COMMIT();
            CP_WAIT(1);
        } else {
            CP_WAIT(0);
        }
        __syncthreads();

        uint32_t st = sbase + (kt & 1) * stageb;
#pragma unroll
        for (int ks = 0; ks < 4; ks++) {
            uint32_t af[4][4];
            uint32_t choA = (((ks * 2 + aci) ^ rl) << 4);
            uint32_t choB = (((ks * 2 + bi) ^ rl) << 4);
#pragma unroll
            for (int mi = 0; mi < 4; mi++)
                ldsm4(af[mi], st + arow[mi] + choA);
            for (int t = 0; t < nt; t++) {
                uint32_t uB = st + TILEB + t * TILEB;
                uint32_t bf[4][2];
#pragma unroll
                for (int ni = 0; ni < 4; ni++)
                    ldsm2(bf[ni], uB + brow[ni] + choB);
#pragma unroll
                for (int mi = 0; mi < 4; mi++)
#pragma unroll
                    for (int ni = 0; ni < 4; ni++)
                        mma_fp(acc[mi][ni], af[mi], bf[ni]);
            }
        }
        __syncthreads();
    }

    int mrow = m0 + wm * 64 + (lane >> 2);
    int ncol = n0 + wn * 32 + (lane & 3) * 2;
#pragma unroll
    for (int mi = 0; mi < 4; mi++) {
#pragma unroll
        for (int ni = 0; ni < 4; ni++) {
            int n = ncol + ni * 8;
#pragma unroll
            for (int half = 0; half < 2; half++) {
                int m = mrow + mi * 16 + half * 8;
                float v0 = acc[mi][ni][half * 2], v1 = acc[mi][ni][half * 2 + 1];
                if (mode == 0) {
                    size_t o = ((size_t)(n >> 6) * L_ + m) * 64 + (n & 63);
                    __half* C = (z == 0) ? g_qh : (z == 1) ? g_kh : g_vh;
                    *(__half2*)(C + o) = __floats2half2_rn(v0, v1);
                } else {
                    *(float2*)(out + (size_t)m * E_ + n) = make_float2(v0, v1);
                }
            }
        }
    }
}

// ============================================================================
// Attention. Grid 512 = 32 q-tiles (heavy first) x 16 heads; 64-row q-tiles.
// 256 thr = 8 warps: 4 m-warps x 2 n-warps. BK=128 k-chunks. 3 CTAs/SM.
// Pass 1: S = q*k mma, e -> g_ef in PV-fragment layout (coalesced 128B/warp).
// Pass 2: T built in registers from g_ef (no smem tile, no ldsm for T);
//         O += T*V (V via ldsm2t); O -> g_aoh fp16.
// ============================================================================
#define AQ_    0u          /* 8 KB: Q (pass1 only) */
#define AKV_   8192u       /* 2 bufs x 16 KB (K 128 rows in pass1, V in pass2) */
#define ABIAS_ 40960u      /* 8 KB */
#define AZP_   49152u      /* 2 x 64 floats */
#define AINVZ_ 49664u
#define ATAUT_ 49920u
#define SMEM_ATT 50176

__global__ void __launch_bounds__(256, 3) attn_kernel(
    const float* __restrict__ bias, const float* __restrict__ tau)
{
    extern __shared__ char smem[];
    uint32_t sb = smem_u32(smem);
    float* sbias = (float*)(smem + ABIAS_);
    float* szp   = (float*)(smem + AZP_);
    float* sinvz = (float*)(smem + AINVZ_);
    float* staut = (float*)(smem + ATAUT_);

    int bx  = blockIdx.x;
    int iq  = 31 - (bx >> 4);       // heavy q-tiles first
    int h   = bx & 15;
    int q0  = iq * 64;
    int nch = (q0 + 64 + 127) >> 7; // 128-row k-chunks covering [0, q0+64)

    int tid = threadIdx.x;
    int lane = tid & 31, w = tid >> 5;
    int wm = w >> 1, wn = w & 1;    // 4 m-warps x 2 n-warps
    int rl = lane & 7;
    int ai = lane >> 3, aci = ai >> 1, bi = ai & 1;
    float tauh = tau[h];
    const float scale = 0.125f;

    for (int i = tid; i < MBL_ / 4; i += 256)
        *(float4*)&sbias[i * 4] = *(const float4*)&bias[h * MBL_ + i * 4];

    const __half* qh = g_qh + (size_t)h * (L_ * 64);
    const __half* kh = g_kh + (size_t)h * (L_ * 64);
    const __half* vh = g_vh + (size_t)h * (L_ * 64);
    uint32_t* efb = g_ef + (size_t)(h * 32 + iq) * (16 * 4096);

    uint32_t arow = (uint32_t)((wm * 16 + (ai & 1) * 8 + rl) * 128);
    uint32_t brow8[8];
#pragma unroll
    for (int ni = 0; ni < 8; ni++)
        brow8[ni] = (uint32_t)((wn * 64 + ni * 8 + rl) * 128);

    // ---- load Q (64 rows x 128B) + K chunk 0 (128 rows x 128B) ----
#pragma unroll
    for (int it = 0; it < 2; it++) {
        int c = tid + it * 256;
        int row = c >> 3, ch = c & 7;
        uint32_t sw = row * 128 + ((ch ^ (row & 7)) << 4);
        cp16(sb + AQ_ + sw, qh + (size_t)(q0 + row) * 64 + ch * 8);
    }
#pragma unroll
    for (int it = 0; it < 4; it++) {
        int c = tid + it * 256;
        int row = c >> 3, ch = c & 7;
        uint32_t sw = row * 128 + ((ch ^ (row & 7)) << 4);
        cp16(sb + AKV_ + sw, kh + (size_t)row * 64 + ch * 8);
    }
    CP_COMMIT();

    float rs[2] = {0.f, 0.f};

    // ==================== PASS 1 ====================
    for (int j = 0; j < nch; j++) {
        int b = j & 1;
        int k0 = j * 128;
        if (j + 1 < nch) {
            uint32_t nb = sb + AKV_ + (b ^ 1) * 16384;
            int k0n = (j + 1) * 128;
#pragma unroll
            for (int it = 0; it < 4; it++) {
                int c = tid + it * 256;
                int row = c >> 3, ch = c & 7;
                uint32_t sw = row * 128 + ((ch ^ (row & 7)) << 4);
                cp16(nb + sw, kh + (size_t)(k0n + row) * 64 + ch * 8);
            }
            CP_COMMIT();
            CP_WAIT(1);
        } else {
            CP_WAIT(0);
        }
        __syncthreads();

        float sacc[8][4];
#pragma unroll
        for (int ni = 0; ni < 8; ni++)
#pragma unroll
            for (int r = 0; r < 4; r++) sacc[ni][r] = 0.f;

        uint32_t bkh = sb + AKV_ + b * 16384;
#pragma unroll
        for (int ks = 0; ks < 4; ks++) {
            uint32_t qf[4];
            uint32_t choA = (((ks * 2 + aci) ^ rl) << 4);
            uint32_t choB = (((ks * 2 + bi) ^ rl) << 4);
            ldsm4(qf, sb + AQ_ + arow + choA);
#pragma unroll
            for (int ni = 0; ni < 8; ni++) {
                uint32_t kf[2];
                ldsm2(kf, bkh + brow8[ni] + choB);
                mma_fp(sacc[ni], qf, kf);
            }
        }
        __syncthreads();    // K buf b reusable

        // epilogue: scale + bias + causal, exp, store e (fragment layout), Z
        int r = wm * 16 + (lane >> 2);
        uint32_t* efj = efb + j * 4096 + wm * 32 + lane;
#pragma unroll
        for (int ni = 0; ni < 8; ni++) {
            int kk = k0 + wn * 64 + ni * 8 + (lane & 3) * 2;
            int slot = wn * 4 + (ni >> 1);
#pragma unroll
            for (int hh = 0; hh < 2; hh++) {
                int qq = q0 + r + hh * 8;
                float s0 = sacc[ni][hh * 2]     * scale;
                float s1 = sacc[ni][hh * 2 + 1] * scale;
                int d0 = qq - kk, d1 = d0 - 1;
                float e0 = (d0 >= 0) ? fexp(s0 + sbias[d0]) : 0.f;
                float e1 = (d1 >= 0) ? fexp(s1 + sbias[d1]) : 0.f;
                __half2 ep = __floats2half2_rn(e0, e1);
                efj[(slot * 4 + (ni & 1) * 2 + hh) * 128] = *(uint32_t*)&ep;
                rs[hh] += e0 + e1;
            }
        }
    }

    // ---- finalize Z ----
#pragma unroll
    for (int hh = 0; hh < 2; hh++) {
        rs[hh] += __shfl_xor_sync(0xffffffffu, rs[hh], 1);
        rs[hh] += __shfl_xor_sync(0xffffffffu, rs[hh], 2);
    }
    if ((lane & 3) == 0) {
        int r0 = wm * 16 + (lane >> 2);
        szp[wn * 64 + r0]     = rs[0];
        szp[wn * 64 + r0 + 8] = rs[1];
    }
    __syncthreads();
    if (tid < 64) {
        float Zr = szp[tid] + szp[64 + tid];
        sinvz[tid] = 1.f / Zr;
        staut[tid] = tauh / (float)(q0 + tid + 1);
    }
    // prefetch V chunk 0 into buf 0
#pragma unroll
    for (int it = 0; it < 4; it++) {
        int c = tid + it * 256;
        int row = c >> 3, ch = c & 7;
        uint32_t sw = row * 128 + ((ch ^ (row & 7)) << 4);
        cp16(sb + AKV_ + sw, vh + (size_t)row * 64 + ch * 8);
    }
    CP_COMMIT();
    __syncthreads();

    // per-thread row constants for pass 2
    int rr = wm * 16 + (lane >> 2);
    float iz0 = sinvz[rr],     tt0 = staut[rr];
    float iz1 = sinvz[rr + 8], tt1 = staut[rr + 8];
    const uint32_t* efr = efb + wm * 32 + lane;

    // ==================== PASS 2 ====================
    float oacc[4][4];
#pragma unroll
    for (int ni = 0; ni < 4; ni++)
#pragma unroll
        for (int r = 0; r < 4; r++) oacc[ni][r] = 0.f;

    for (int j = 0; j < nch; j++) {
        int b = j & 1;
        if (j + 1 < nch) {
            uint32_t nb = sb + AKV_ + (b ^ 1) * 16384;
            int k0n = (j + 1) * 128;
#pragma unroll
            for (int it = 0; it < 4; it++) {
                int c = tid + it * 256;
                int row = c >> 3, ch = c & 7;
                uint32_t sw = row * 128 + ((ch ^ (row & 7)) << 4);
                cp16(nb + sw, vh + (size_t)(k0n + row) * 64 + ch * 8);
            }
            CP_COMMIT();
            CP_WAIT(1);
        } else {
            CP_WAIT(0);
        }
        __syncthreads();

        const uint32_t* efc = efr + j * 4096;
        uint32_t bv = sb + AKV_ + b * 16384;
        int krl = lane & 15;
#pragma unroll
        for (int ks = 0; ks < 8; ks++) {
            uint32_t tf[4], vf[4][2];
            tf[0] = trelu2(efc[(ks * 4 + 0) * 128], iz0, tt0);
            tf[1] = trelu2(efc[(ks * 4 + 1) * 128], iz1, tt1);
            tf[2] = trelu2(efc[(ks * 4 + 2) * 128], iz0, tt0);
            tf[3] = trelu2(efc[(ks * 4 + 3) * 128], iz1, tt1);
            int kr = ks * 16 + krl;              // 0..127 V rows
#pragma unroll
            for (int ni = 0; ni < 4; ni++) {
                uint32_t off = kr * 128 + (((wn * 4 + ni) ^ (kr & 7)) << 4);
                ldsm2t(vf[ni], bv + off);
            }
#pragma unroll
            for (int ni = 0; ni < 4; ni++)
                mma_fp(oacc[ni], tf, vf[ni]);
        }
        __syncthreads();    // V buf free for next chunk
    }

    // ---- O -> g_aoh fp16 ----
#pragma unroll
    for (int ni = 0; ni < 4; ni++) {
        int c = wn * 32 + ni * 8 + (lane & 3) * 2;
#pragma unroll
        for (int hh = 0; hh < 2; hh++) {
            int q = q0 + wm * 16 + (lane >> 2) + hh * 8;
            float v0 = oacc[ni][hh * 2], v1 = oacc[ni][hh * 2 + 1];
            size_t o = (size_t)q * E_ + h * 64 + c;
            *(__half2*)(g_aoh + o) = __floats2half2_rn(v0, v1);
        }
    }
}

// ============================================================================
extern "C" void kernel_launch(void* const* d_in, const int* in_sizes, int n_in,
                              void* d_out, int out_size)
{
    (void)in_sizes; (void)n_in; (void)out_size;
    const float* x    = (const float*)d_in[0];
    const float* Wq   = (const float*)d_in[1];
    const float* Wk   = (const float*)d_in[2];
    const float* Wv   = (const float*)d_in[3];
    const float* Wo   = (const float*)d_in[4];
    const float* bias = (const float*)d_in[5];
    const float* tau  = (const float*)d_in[6];
    float* out = (float*)d_out;

    cudaFuncSetAttribute(mma_gemm, cudaFuncAttributeMaxDynamicSharedMemorySize, SMEM_MMA2);
    cudaFuncSetAttribute(attn_kernel, cudaFuncAttributeMaxDynamicSharedMemorySize, SMEM_ATT);

    conv_all<<<2048 + 4 * 1024, 256>>>(x, Wq, Wk, Wv, Wo);
    mma_gemm<<<dim3(E_ / 128, L_ / 128, 3), 256, SMEM_MMA1>>>(0, nullptr);
    attn_kernel<<<512, 256, SMEM_ATT>>>(bias, tau);
    mma_gemm<<<dim3(E_ / 128, L_ / 128, 1), 256, SMEM_MMA2>>>(1, out);
}